// round 7
// baseline (speedup 1.0000x reference)
#include <cuda_runtime.h>
#include <cuda_bf16.h>
#include <cstdint>

#define BB   32
#define CC   16
#define HH   256
#define WWID 256
#define PP   144
#define HID  128
#define LL   16384
#define NT   8192      // tiles: 64 positions each
#define NCTA 152
#define NTHR 512

// Scratch for out_p, layout (B, P, L) fp32 = 302 MB
__device__ float g_outp[(size_t)BB * PP * LL];

// ---------------- smem byte offsets ----------------
#define OFF_B1H 0
#define OFF_B1L 38912              // 128 x 152 x 2B
#define OFF_B2H 77824
#define OFF_B2L 116992             // 144 x 136 x 2B
#define OFF_AH  156160             // 64 x 152 x 2B (A1) / 64 x 136 x 2B (A2)
#define OFF_AL  175616
#define OFF_b1  195072
#define OFF_b2  195584
#define SMEM_TOT 196160
#define AS1 152                    // 304B rows: 19*16B -> conflict-free ldmatrix
#define AS2 136                    // 272B rows: 17*16B
#define DB1 38912                  // hi->lo delta, B1
#define DB2 39168                  // hi->lo delta, B2
#define DA  19456                  // hi->lo delta, A

// ---------------- helpers ----------------
__device__ __forceinline__ uint32_t smem_u32(const void* p) {
    uint32_t a;
    asm("{ .reg .u64 t; cvta.to.shared.u64 t, %1; cvt.u32.u64 %0, t; }" : "=r"(a) : "l"(p));
    return a;
}
__device__ __forceinline__ void ldsm4(uint32_t* r, uint32_t a) {
    asm volatile("ldmatrix.sync.aligned.m8n8.x4.shared.b16 {%0,%1,%2,%3}, [%4];"
                 : "=r"(r[0]), "=r"(r[1]), "=r"(r[2]), "=r"(r[3]) : "r"(a));
}
__device__ __forceinline__ void ldsm2(uint32_t* r, uint32_t a) {
    asm volatile("ldmatrix.sync.aligned.m8n8.x2.shared.b16 {%0,%1}, [%2];"
                 : "=r"(r[0]), "=r"(r[1]) : "r"(a));
}
__device__ __forceinline__ void mma_bf16(float* d, const uint32_t* a, uint32_t b0, uint32_t b1) {
    asm volatile("mma.sync.aligned.m16n8k16.row.col.f32.bf16.bf16.f32 "
                 "{%0,%1,%2,%3}, {%4,%5,%6,%7}, {%8,%9}, {%0,%1,%2,%3};"
                 : "+f"(d[0]), "+f"(d[1]), "+f"(d[2]), "+f"(d[3])
                 : "r"(a[0]), "r"(a[1]), "r"(a[2]), "r"(a[3]), "r"(b0), "r"(b1));
}
__device__ __forceinline__ uint32_t cvt2(float lo_v, float hi_v) {
    uint32_t d;
    asm("cvt.rn.bf16x2.f32 %0, %1, %2;" : "=r"(d) : "f"(hi_v), "f"(lo_v));
    return d;
}
// split v0,v1 -> packed hi bf16x2 (return) and packed lo bf16x2 (out param)
__device__ __forceinline__ uint32_t split_pack(float v0, float v1, uint32_t& lo) {
    uint32_t hi = cvt2(v0, v1);
    float h0 = __uint_as_float(hi << 16);
    float h1 = __uint_as_float(hi & 0xffff0000u);
    lo = cvt2(v0 - h0, v1 - h1);
    return hi;
}
__device__ __forceinline__ void split_sts(char* hi_base, uint32_t off, uint32_t lodelta, float v) {
    __nv_bfloat16 h = __float2bfloat16(v);
    __nv_bfloat16 l = __float2bfloat16(v - __bfloat162float(h));
    *(uint16_t*)(hi_base + off) = *(uint16_t*)&h;
    *(uint16_t*)(hi_base + lodelta + off) = *(uint16_t*)&l;
}
__device__ __forceinline__ int refl(int v, int n) {
    return (v < 0) ? -v : ((v >= n) ? 2 * n - 2 - v : v);
}

// ---------------------------------------------------------------------------
// Persistent MLP kernel. grid = NCTA, 512 threads (16 warps, 4m x 4n grid).
// Tile = 64 positions. Weights staged once. Output layout (B, P, L).
// ---------------------------------------------------------------------------
__global__ __launch_bounds__(NTHR, 1)
void mlp_persist(const float* __restrict__ x, const float* __restrict__ W1,
                 const float* __restrict__ b1, const float* __restrict__ W2,
                 const float* __restrict__ b2) {
    extern __shared__ char smem[];
    const uint32_t sb = smem_u32(smem);
    const int tid = threadIdx.x;
    const int wid = tid >> 5, lid = tid & 31;

    float* b1s = (float*)(smem + OFF_b1);
    float* b2s = (float*)(smem + OFF_b2);
    if (tid < 128) b1s[tid] = b1[tid];
    if (tid < 144) b2s[tid] = b2[tid];

    // ---- stage W1^T and W2^T (split) ONCE ----
    #pragma unroll 4
    for (int i = 0; i < 36; i++) {
        int e = i * NTHR + tid;              // e = k*128 + n
        int k = e >> 7, n = e & 127;
        split_sts(smem + OFF_B1H, (uint32_t)(n * AS1 + k) * 2, DB1, __ldg(&W1[e]));
    }
    #pragma unroll 4
    for (int i = 0; i < 36; i++) {
        int e = i * NTHR + tid;              // e = k*144 + n
        int k = e / 144, n = e - k * 144;
        split_sts(smem + OFF_B2H, (uint32_t)(n * AS2 + k) * 2, DB2, __ldg(&W2[e]));
    }

    // warp tiling constants: 4 m-tiles of 16 rows, 4 n-groups
    const int wm = (wid & 3) * 16;
    const int wn = wid >> 2;
    const int g = lid >> 3, r = lid & 7;
    const int khalf = (g >> 1) * 8;
    const int arow = wm + (g & 1) * 8 + r;
    const int g2 = (lid >> 3) & 1;

    // GEMM2 N-tile split: 18 n8-tiles over 4 warps: [5,5,4,4]
    const int nt2   = (wn < 2) ? 5 : 4;
    const int base2 = wn * 4 + ((wn < 2) ? wn : 2);   // 0,5,10,14

    // gather mapping: pos = tid>>3 (64 pos), oct = tid&7 -> 18 p-elems
    const int pos = tid >> 3;
    const int oct = tid & 7;
    const int pb  = oct * 18;

    float xv[18];

    // ---- prefetch first tile ----
    {
        int t = blockIdx.x;
        int b = t >> 8, rem = t & 255, ho = rem >> 1, wo0 = (rem & 1) * 64;
        const float* xb = x + ((size_t)b * CC + oct * 2) * (HH * WWID);
        int rw[3], cl[3];
        #pragma unroll
        for (int kk = 0; kk < 3; kk++) {
            rw[kk] = refl(2 * ho + kk - 1, HH) * WWID;
            cl[kk] = refl(2 * (wo0 + pos) + kk - 1, WWID);
        }
        #pragma unroll
        for (int ci = 0; ci < 2; ci++) {
            const float* xc = xb + ci * (HH * WWID);
            #pragma unroll
            for (int kh = 0; kh < 3; kh++)
                #pragma unroll
                for (int kw = 0; kw < 3; kw++)
                    xv[ci * 9 + kh * 3 + kw] = __ldg(&xc[rw[kh] + cl[kw]]);
        }
    }

    for (int t = blockIdx.x; t < NT; t += NCTA) {
        const int b = t >> 8, rem = t & 255, ho = rem >> 1, wo0 = (rem & 1) * 64;

        __syncthreads();   // prev GEMM2 done reading A buffer
        // ---- store A1 (split) ----
        #pragma unroll
        for (int i = 0; i < 9; i++) {
            uint32_t lo, hi = split_pack(xv[2 * i], xv[2 * i + 1], lo);
            uint32_t off = (uint32_t)(pos * AS1 + pb + 2 * i) * 2;
            *(uint32_t*)(smem + OFF_AH + off) = hi;
            *(uint32_t*)(smem + OFF_AL + off) = lo;
        }
        __syncthreads();

        // ---- GEMM1: D1[64 x 128], warp covers 16m x 32n ----
        float d1[4][4];
        #pragma unroll
        for (int nj = 0; nj < 4; nj++)
            #pragma unroll
            for (int p = 0; p < 4; p++) d1[nj][p] = 0.f;
        {
            uint32_t pA = sb + OFF_AH + (uint32_t)(arow * AS1 + khalf) * 2;
            uint32_t pB[2];
            #pragma unroll
            for (int np = 0; np < 2; np++)
                pB[np] = sb + OFF_B1H + (uint32_t)((wn * 32 + np * 16 + (g & 1) * 8 + r) * AS1 + khalf) * 2;

            uint32_t a[4], bA[2][4], bB[2][4];
            #pragma unroll
            for (int ks = 0; ks < 9; ks++) {
                const uint32_t ko = ks * 32;
                ldsm4(a, pA + ko);
                #pragma unroll
                for (int np = 0; np < 2; np++) ldsm4(bA[np], pB[np] + ko);
                #pragma unroll
                for (int np = 0; np < 2; np++) {
                    mma_bf16(d1[np * 2],     a, bA[np][0], bA[np][2]);
                    mma_bf16(d1[np * 2 + 1], a, bA[np][1], bA[np][3]);
                }
                #pragma unroll
                for (int np = 0; np < 2; np++) ldsm4(bB[np], pB[np] + DB1 + ko);
                #pragma unroll
                for (int np = 0; np < 2; np++) {
                    mma_bf16(d1[np * 2],     a, bB[np][0], bB[np][2]);
                    mma_bf16(d1[np * 2 + 1], a, bB[np][1], bB[np][3]);
                }
                ldsm4(a, pA + DA + ko);
                #pragma unroll
                for (int np = 0; np < 2; np++) {
                    mma_bf16(d1[np * 2],     a, bA[np][0], bA[np][2]);
                    mma_bf16(d1[np * 2 + 1], a, bA[np][1], bA[np][3]);
                }
            }
        }
        __syncthreads();   // all warps done reading A1

        // ---- epi1: relu(D1+b1) split -> A2 (stride AS2) ----
        {
            const int r0 = lid >> 2;
            const int c0 = (lid & 3) * 2;
            #pragma unroll
            for (int nj = 0; nj < 4; nj++) {
                const int col = wn * 32 + nj * 8 + c0;
                const float bb0 = b1s[col], bb1 = b1s[col + 1];
                float v0 = d1[nj][0] + bb0; v0 = v0 > 0.f ? v0 : 0.f;
                float v1 = d1[nj][1] + bb1; v1 = v1 > 0.f ? v1 : 0.f;
                float v2 = d1[nj][2] + bb0; v2 = v2 > 0.f ? v2 : 0.f;
                float v3 = d1[nj][3] + bb1; v3 = v3 > 0.f ? v3 : 0.f;
                uint32_t lo, hi;
                uint32_t offA = (uint32_t)((wm + r0) * AS2 + col) * 2;
                hi = split_pack(v0, v1, lo);
                *(uint32_t*)(smem + OFF_AH + offA) = hi;
                *(uint32_t*)(smem + OFF_AL + offA) = lo;
                uint32_t offB = (uint32_t)((wm + r0 + 8) * AS2 + col) * 2;
                hi = split_pack(v2, v3, lo);
                *(uint32_t*)(smem + OFF_AH + offB) = hi;
                *(uint32_t*)(smem + OFF_AL + offB) = lo;
            }
        }

        // ---- prefetch next tile (overlaps GEMM2) ----
        {
            int tn = t + NCTA;
            if (tn < NT) {
                int bn = tn >> 8, remn = tn & 255, hon = remn >> 1, wo0n = (remn & 1) * 64;
                const float* xb = x + ((size_t)bn * CC + oct * 2) * (HH * WWID);
                int rw[3], cl[3];
                #pragma unroll
                for (int kk = 0; kk < 3; kk++) {
                    rw[kk] = refl(2 * hon + kk - 1, HH) * WWID;
                    cl[kk] = refl(2 * (wo0n + pos) + kk - 1, WWID);
                }
                #pragma unroll
                for (int ci = 0; ci < 2; ci++) {
                    const float* xc = xb + ci * (HH * WWID);
                    #pragma unroll
                    for (int kh = 0; kh < 3; kh++)
                        #pragma unroll
                        for (int kw = 0; kw < 3; kw++)
                            xv[ci * 9 + kh * 3 + kw] = __ldg(&xc[rw[kh] + cl[kw]]);
                }
            }
        }
        __syncthreads();   // A2 visible

        // ---- GEMM2: D2[64 x 144], warp covers 16m x (nt2*8)n ----
        float d2[5][4];
        #pragma unroll
        for (int nj = 0; nj < 5; nj++)
            #pragma unroll
            for (int p = 0; p < 4; p++) d2[nj][p] = 0.f;
        {
            uint32_t pA = sb + OFF_AH + (uint32_t)(arow * AS2 + khalf) * 2;
            uint32_t pB[2], pS;
            #pragma unroll
            for (int np = 0; np < 2; np++)
                pB[np] = sb + OFF_B2H + (uint32_t)((base2 * 8 + np * 16 + (g & 1) * 8 + r) * AS2 + khalf) * 2;
            pS = sb + OFF_B2H + (uint32_t)(((base2 + 4) * 8 + r) * AS2 + g2 * 8) * 2;

            uint32_t a[4], bA[2][4], bB[2][4], sA[2], sB[2];
            #pragma unroll
            for (int ks = 0; ks < 8; ks++) {
                const uint32_t ko = ks * 32;
                ldsm4(a, pA + ko);
                #pragma unroll
                for (int np = 0; np < 2; np++) ldsm4(bA[np], pB[np] + ko);
                if (nt2 == 5) ldsm2(sA, pS + ko);
                #pragma unroll
                for (int np = 0; np < 2; np++) {
                    mma_bf16(d2[np * 2],     a, bA[np][0], bA[np][2]);
                    mma_bf16(d2[np * 2 + 1], a, bA[np][1], bA[np][3]);
                }
                if (nt2 == 5) mma_bf16(d2[4], a, sA[0], sA[1]);
                #pragma unroll
                for (int np = 0; np < 2; np++) ldsm4(bB[np], pB[np] + DB2 + ko);
                if (nt2 == 5) ldsm2(sB, pS + DB2 + ko);
                #pragma unroll
                for (int np = 0; np < 2; np++) {
                    mma_bf16(d2[np * 2],     a, bB[np][0], bB[np][2]);
                    mma_bf16(d2[np * 2 + 1], a, bB[np][1], bB[np][3]);
                }
                if (nt2 == 5) mma_bf16(d2[4], a, sB[0], sB[1]);
                ldsm4(a, pA + DA + ko);
                #pragma unroll
                for (int np = 0; np < 2; np++) {
                    mma_bf16(d2[np * 2],     a, bA[np][0], bA[np][2]);
                    mma_bf16(d2[np * 2 + 1], a, bA[np][1], bA[np][3]);
                }
                if (nt2 == 5) mma_bf16(d2[4], a, sA[0], sA[1]);
            }
        }

        // ---- epi2: D2 + b2 -> g_outp[b][col][pos] (coalesced 32B runs) ----
        {
            const int r0 = lid >> 2;
            const int c0 = (lid & 3) * 2;
            float* ob = g_outp + (size_t)b * PP * LL + (size_t)ho * 128 + wo0;
            const int posA = wm + r0;
            const int posB = posA + 8;
            #pragma unroll
            for (int nj = 0; nj < 5; nj++) {
                if (nj < nt2) {
                    const int col = (base2 + nj) * 8 + c0;
                    const float bb0 = b2s[col], bb1 = b2s[col + 1];
                    float* c0p = ob + (size_t)col * LL;
                    float* c1p = c0p + LL;
                    c0p[posA] = d2[nj][0] + bb0;
                    c1p[posA] = d2[nj][1] + bb1;
                    c0p[posB] = d2[nj][2] + bb0;
                    c1p[posB] = d2[nj][3] + bb1;
                }
            }
        }
    }
}

// ---------------------------------------------------------------------------
// Kernel B: gather-fold + normalize + channel mix + softmax + modulate
// ---------------------------------------------------------------------------
__global__ __launch_bounds__(256)
void fold_softmax_kernel(const float* __restrict__ Wc, const float* __restrict__ bc,
                         float* __restrict__ out) {
    __shared__ float sWc[256];
    __shared__ float sbc[16];
    int tid = threadIdx.x;
    sWc[tid] = Wc[tid];
    if (tid < 16) sbc[tid] = bc[tid];
    __syncthreads();

    const int b = blockIdx.x >> 8;
    const int i = (blockIdx.x & 255) + 1;   // padded row in [1,256]
    const int j = tid + 1;                  // padded col in [1,256]

    int khA[2], hoA[2], nh = 0;
    #pragma unroll
    for (int kh = 0; kh < 3; kh++) {
        int t = i - kh;
        if (t >= 0 && t <= 254 && !(t & 1)) { khA[nh] = kh; hoA[nh] = t >> 1; nh++; }
    }
    int kwA[2], woA[2], nw = 0;
    #pragma unroll
    for (int kw = 0; kw < 3; kw++) {
        int t = j - kw;
        if (t >= 0 && t <= 254 && !(t & 1)) { kwA[nw] = kw; woA[nw] = t >> 1; nw++; }
    }

    float nrm[16];
    #pragma unroll
    for (int c = 0; c < 16; c++) nrm[c] = 0.f;

    const float* gb = g_outp + (size_t)b * PP * LL;
    for (int a = 0; a < nh; a++)
        for (int d = 0; d < nw; d++) {
            const float* rec = gb + (size_t)(khA[a] * 3 + kwA[d]) * LL
                             + hoA[a] * 128 + woA[d];
            #pragma unroll
            for (int c = 0; c < 16; c++) nrm[c] += rec[(size_t)c * 9 * LL];
        }

    const float inv = 1.f / ((float)(nh * nw) + 1e-6f);
    #pragma unroll
    for (int c = 0; c < 16; c++) nrm[c] *= inv;

    float logit[16];
    #pragma unroll
    for (int o = 0; o < 16; o++) {
        float s = sbc[o];
        #pragma unroll
        for (int c = 0; c < 16; c++) s += sWc[o * 16 + c] * nrm[c];
        logit[o] = s;
    }
    float m = logit[0];
    #pragma unroll
    for (int o = 1; o < 16; o++) m = fmaxf(m, logit[o]);
    float e[16], sum = 0.f;
    #pragma unroll
    for (int o = 0; o < 16; o++) { e[o] = __expf(logit[o] - m); sum += e[o]; }
    const float rs = 1.f / sum;

    float* ob = out + (size_t)b * CC * HH * WWID + (size_t)(i - 1) * WWID + (j - 1);
    #pragma unroll
    for (int c = 0; c < 16; c++) ob[(size_t)c * HH * WWID] = nrm[c] * e[c] * rs;
}

// ---------------------------------------------------------------------------
extern "C" void kernel_launch(void* const* d_in, const int* in_sizes, int n_in,
                              void* d_out, int out_size) {
    const float* x  = (const float*)d_in[0];
    const float* W1 = (const float*)d_in[1];
    const float* b1 = (const float*)d_in[2];
    const float* W2 = (const float*)d_in[3];
    const float* b2 = (const float*)d_in[4];
    const float* Wc = (const float*)d_in[5];
    const float* bc = (const float*)d_in[6];
    float* out = (float*)d_out;

    cudaFuncSetAttribute(mlp_persist, cudaFuncAttributeMaxDynamicSharedMemorySize, SMEM_TOT);

    mlp_persist<<<NCTA, NTHR, SMEM_TOT>>>(x, W1, b1, W2, b2);
    fold_softmax_kernel<<<BB * 256, 256>>>(Wc, bc, out);
}

// round 8
// speedup vs baseline: 1.2060x; 1.2060x over previous
#include <cuda_runtime.h>
#include <cuda_fp16.h>
#include <cstdint>

#define BB   32
#define CC   16
#define HH   256
#define WWID 256
#define PP   144
#define HID  128
#define LL   16384
#define NT   8192      // tiles: 64 positions each
#define NCTA 152

// Scratch for out_p, layout (B, P, L) fp32 = 302 MB
__device__ float g_outp[(size_t)BB * PP * LL];

// ---------------- smem byte offsets ----------------
#define OFF_B1H 0                  // 128 x 152 x 2B = 38912 (fp16 W1^T)
#define OFF_B2H 38912              // 144 x 136 x 2B = 39168 (fp16 W2^T)
#define OFF_AH  78080              // 64 x 152 x 2B = 19456 (A hi)
#define OFF_AL  97536              // 19456 (A lo)
#define OFF_b1  116992             // 512
#define OFF_b2  117504             // 576
#define SMEM_TOT 118144
#define AS1 152                    // 304B rows: 19*16B -> conflict-free ldmatrix
#define AS2 136                    // 272B rows: 17*16B
#define DA  19456                  // A hi->lo delta

// ---------------- helpers ----------------
__device__ __forceinline__ uint32_t smem_u32(const void* p) {
    uint32_t a;
    asm("{ .reg .u64 t; cvta.to.shared.u64 t, %1; cvt.u32.u64 %0, t; }" : "=r"(a) : "l"(p));
    return a;
}
__device__ __forceinline__ void ldsm4(uint32_t* r, uint32_t a) {
    asm volatile("ldmatrix.sync.aligned.m8n8.x4.shared.b16 {%0,%1,%2,%3}, [%4];"
                 : "=r"(r[0]), "=r"(r[1]), "=r"(r[2]), "=r"(r[3]) : "r"(a));
}
__device__ __forceinline__ void ldsm2(uint32_t* r, uint32_t a) {
    asm volatile("ldmatrix.sync.aligned.m8n8.x2.shared.b16 {%0,%1}, [%2];"
                 : "=r"(r[0]), "=r"(r[1]) : "r"(a));
}
__device__ __forceinline__ void mma_f16(float* d, const uint32_t* a, uint32_t b0, uint32_t b1) {
    asm volatile("mma.sync.aligned.m16n8k16.row.col.f32.f16.f16.f32 "
                 "{%0,%1,%2,%3}, {%4,%5,%6,%7}, {%8,%9}, {%0,%1,%2,%3};"
                 : "+f"(d[0]), "+f"(d[1]), "+f"(d[2]), "+f"(d[3])
                 : "r"(a[0]), "r"(a[1]), "r"(a[2]), "r"(a[3]), "r"(b0), "r"(b1));
}
__device__ __forceinline__ uint32_t packh(__half a, __half b) {
    return (uint32_t)*(uint16_t*)&a | ((uint32_t)*(uint16_t*)&b << 16);
}
// split v0,v1 -> packed hi f16x2 (return) and packed lo f16x2 (out param)
__device__ __forceinline__ uint32_t split_pack(float v0, float v1, uint32_t& lo) {
    __half h0 = __float2half_rn(v0), h1 = __float2half_rn(v1);
    __half l0 = __float2half_rn(v0 - __half2float(h0));
    __half l1 = __float2half_rn(v1 - __half2float(h1));
    lo = packh(l0, l1);
    return packh(h0, h1);
}
__device__ __forceinline__ int refl(int v, int n) {
    return (v < 0) ? -v : ((v >= n) ? 2 * n - 2 - v : v);
}

// ---------------------------------------------------------------------------
// Persistent MLP kernel. grid = NCTA, 256 threads (8 warps: 4m x 2n).
// fp16 2-pass: D = (A_hi + A_lo) @ B_fp16. Tile = 64 positions.
// ---------------------------------------------------------------------------
__global__ __launch_bounds__(256, 1)
void mlp_persist(const float* __restrict__ x, const float* __restrict__ W1,
                 const float* __restrict__ b1, const float* __restrict__ W2,
                 const float* __restrict__ b2) {
    extern __shared__ char smem[];
    const uint32_t sb = smem_u32(smem);
    const int tid = threadIdx.x;
    const int wid = tid >> 5, lid = tid & 31;

    float* b1s = (float*)(smem + OFF_b1);
    float* b2s = (float*)(smem + OFF_b2);
    if (tid < 128) b1s[tid] = b1[tid];
    if (tid < 144) b2s[tid] = b2[tid];

    // ---- stage fp16 W1^T and W2^T ONCE ----
    #pragma unroll 4
    for (int i = 0; i < 72; i++) {
        int e = i * 256 + tid;               // e = k*128 + n
        int k = e >> 7, n = e & 127;
        *(uint16_t*)(smem + OFF_B1H + (uint32_t)(n * AS1 + k) * 2) =
            *(uint16_t*)&(__half)__float2half_rn(__ldg(&W1[e]));
    }
    #pragma unroll 4
    for (int i = 0; i < 72; i++) {
        int e = i * 256 + tid;               // e = k*144 + n
        int k = e / 144, n = e - k * 144;
        *(uint16_t*)(smem + OFF_B2H + (uint32_t)(n * AS2 + k) * 2) =
            *(uint16_t*)&(__half)__float2half_rn(__ldg(&W2[e]));
    }

    // warp tiling constants
    const int wm = (wid & 3) * 16;
    const int wn = wid >> 2;
    const int g = lid >> 3, r = lid & 7;
    const int khalf = (g >> 1) * 8;
    const int arow = wm + (g & 1) * 8 + r;
    const int g2 = (lid >> 3) & 1;

    // gather mapping: pos = tid>>2 (64 pos), quarter q = tid&3 -> 36 p-elems
    const int pos = tid >> 2;
    const int q   = tid & 3;
    const int pb  = q * 36;

    float xv[36];

    // ---- prefetch first tile ----
    {
        int t = blockIdx.x;
        int b = t >> 8, rem = t & 255, ho = rem >> 1, wo0 = (rem & 1) * 64;
        const float* xb = x + ((size_t)b * CC + q * 4) * (HH * WWID);
        int rw[3], cl[3];
        #pragma unroll
        for (int kk = 0; kk < 3; kk++) {
            rw[kk] = refl(2 * ho + kk - 1, HH) * WWID;
            cl[kk] = refl(2 * (wo0 + pos) + kk - 1, WWID);
        }
        #pragma unroll
        for (int ci = 0; ci < 4; ci++) {
            const float* xc = xb + ci * (HH * WWID);
            #pragma unroll
            for (int kh = 0; kh < 3; kh++)
                #pragma unroll
                for (int kw = 0; kw < 3; kw++)
                    xv[ci * 9 + kh * 3 + kw] = __ldg(&xc[rw[kh] + cl[kw]]);
        }
    }

    for (int t = blockIdx.x; t < NT; t += NCTA) {
        const int b = t >> 8, rem = t & 255, ho = rem >> 1, wo0 = (rem & 1) * 64;

        __syncthreads();   // prev GEMM2 done reading A buffer
        // ---- store A1 (split) ----
        #pragma unroll
        for (int i = 0; i < 18; i++) {
            uint32_t lo, hi = split_pack(xv[2 * i], xv[2 * i + 1], lo);
            uint32_t off = (uint32_t)(pos * AS1 + pb + 2 * i) * 2;
            *(uint32_t*)(smem + OFF_AH + off) = hi;
            *(uint32_t*)(smem + OFF_AL + off) = lo;
        }
        __syncthreads();

        // ---- GEMM1: D1[64 x 128], warp covers 16m x 64n, 2 A-passes ----
        float d1[8][4];
        #pragma unroll
        for (int nj = 0; nj < 8; nj++)
            #pragma unroll
            for (int p = 0; p < 4; p++) d1[nj][p] = 0.f;
        {
            uint32_t pA = sb + OFF_AH + (uint32_t)(arow * AS1 + khalf) * 2;
            uint32_t pB[4];
            #pragma unroll
            for (int np = 0; np < 4; np++)
                pB[np] = sb + OFF_B1H + (uint32_t)((wn * 64 + np * 16 + (g & 1) * 8 + r) * AS1 + khalf) * 2;

            uint32_t a[4], bA[4][4];
            #pragma unroll
            for (int ks = 0; ks < 9; ks++) {
                const uint32_t ko = ks * 32;
                ldsm4(a, pA + ko);
                #pragma unroll
                for (int np = 0; np < 4; np++) ldsm4(bA[np], pB[np] + ko);
                #pragma unroll
                for (int np = 0; np < 4; np++) {
                    mma_f16(d1[np * 2],     a, bA[np][0], bA[np][2]);
                    mma_f16(d1[np * 2 + 1], a, bA[np][1], bA[np][3]);
                }
                ldsm4(a, pA + DA + ko);
                #pragma unroll
                for (int np = 0; np < 4; np++) {
                    mma_f16(d1[np * 2],     a, bA[np][0], bA[np][2]);
                    mma_f16(d1[np * 2 + 1], a, bA[np][1], bA[np][3]);
                }
            }
        }
        __syncthreads();   // all warps done reading A1

        // ---- epi1: relu(D1+b1) split -> A2 (stride AS2) ----
        {
            const int r0 = lid >> 2;
            const int c0 = (lid & 3) * 2;
            #pragma unroll
            for (int nj = 0; nj < 8; nj++) {
                const int col = wn * 64 + nj * 8 + c0;
                const float bb0 = b1s[col], bb1 = b1s[col + 1];
                float v0 = d1[nj][0] + bb0; v0 = v0 > 0.f ? v0 : 0.f;
                float v1 = d1[nj][1] + bb1; v1 = v1 > 0.f ? v1 : 0.f;
                float v2 = d1[nj][2] + bb0; v2 = v2 > 0.f ? v2 : 0.f;
                float v3 = d1[nj][3] + bb1; v3 = v3 > 0.f ? v3 : 0.f;
                uint32_t lo, hi;
                uint32_t offA = (uint32_t)((wm + r0) * AS2 + col) * 2;
                hi = split_pack(v0, v1, lo);
                *(uint32_t*)(smem + OFF_AH + offA) = hi;
                *(uint32_t*)(smem + OFF_AL + offA) = lo;
                uint32_t offB = (uint32_t)((wm + r0 + 8) * AS2 + col) * 2;
                hi = split_pack(v2, v3, lo);
                *(uint32_t*)(smem + OFF_AH + offB) = hi;
                *(uint32_t*)(smem + OFF_AL + offB) = lo;
            }
        }

        // ---- prefetch next tile (overlaps GEMM2) ----
        {
            int tn = t + NCTA;
            if (tn < NT) {
                int bn = tn >> 8, remn = tn & 255, hon = remn >> 1, wo0n = (remn & 1) * 64;
                const float* xb = x + ((size_t)bn * CC + q * 4) * (HH * WWID);
                int rw[3], cl[3];
                #pragma unroll
                for (int kk = 0; kk < 3; kk++) {
                    rw[kk] = refl(2 * hon + kk - 1, HH) * WWID;
                    cl[kk] = refl(2 * (wo0n + pos) + kk - 1, WWID);
                }
                #pragma unroll
                for (int ci = 0; ci < 4; ci++) {
                    const float* xc = xb + ci * (HH * WWID);
                    #pragma unroll
                    for (int kh = 0; kh < 3; kh++)
                        #pragma unroll
                        for (int kw = 0; kw < 3; kw++)
                            xv[ci * 9 + kh * 3 + kw] = __ldg(&xc[rw[kh] + cl[kw]]);
                }
            }
        }
        __syncthreads();   // A2 visible

        // ---- GEMM2: D2[64 x 144], warp covers 16m x 72n, 2 A-passes ----
        float d2[9][4];
        #pragma unroll
        for (int nj = 0; nj < 9; nj++)
            #pragma unroll
            for (int p = 0; p < 4; p++) d2[nj][p] = 0.f;
        {
            uint32_t pA = sb + OFF_AH + (uint32_t)(arow * AS2 + khalf) * 2;
            uint32_t pB[4], pS;
            #pragma unroll
            for (int np = 0; np < 4; np++)
                pB[np] = sb + OFF_B2H + (uint32_t)((wn * 72 + np * 16 + (g & 1) * 8 + r) * AS2 + khalf) * 2;
            pS = sb + OFF_B2H + (uint32_t)((wn * 72 + 64 + r) * AS2 + g2 * 8) * 2;

            uint32_t a[4], bA[4][4], sA[2];
            #pragma unroll
            for (int ks = 0; ks < 8; ks++) {
                const uint32_t ko = ks * 32;
                ldsm4(a, pA + ko);
                #pragma unroll
                for (int np = 0; np < 4; np++) ldsm4(bA[np], pB[np] + ko);
                ldsm2(sA, pS + ko);
                #pragma unroll
                for (int np = 0; np < 4; np++) {
                    mma_f16(d2[np * 2],     a, bA[np][0], bA[np][2]);
                    mma_f16(d2[np * 2 + 1], a, bA[np][1], bA[np][3]);
                }
                mma_f16(d2[8], a, sA[0], sA[1]);
                ldsm4(a, pA + DA + ko);
                #pragma unroll
                for (int np = 0; np < 4; np++) {
                    mma_f16(d2[np * 2],     a, bA[np][0], bA[np][2]);
                    mma_f16(d2[np * 2 + 1], a, bA[np][1], bA[np][3]);
                }
                mma_f16(d2[8], a, sA[0], sA[1]);
            }
        }

        // ---- epi2: D2 + b2 -> g_outp[b][col][pos] (coalesced 32B runs) ----
        {
            const int r0 = lid >> 2;
            const int c0 = (lid & 3) * 2;
            float* ob = g_outp + (size_t)b * PP * LL + (size_t)ho * 128 + wo0;
            const int posA = wm + r0;
            const int posB = posA + 8;
            #pragma unroll
            for (int nj = 0; nj < 9; nj++) {
                const int col = wn * 72 + nj * 8 + c0;
                const float bb0 = b2s[col], bb1 = b2s[col + 1];
                float* c0p = ob + (size_t)col * LL;
                float* c1p = c0p + LL;
                c0p[posA] = d2[nj][0] + bb0;
                c1p[posA] = d2[nj][1] + bb1;
                c0p[posB] = d2[nj][2] + bb0;
                c1p[posB] = d2[nj][3] + bb1;
            }
        }
    }
}

// ---------------------------------------------------------------------------
// Kernel B: gather-fold + normalize + channel mix + softmax + modulate
// ---------------------------------------------------------------------------
__global__ __launch_bounds__(256)
void fold_softmax_kernel(const float* __restrict__ Wc, const float* __restrict__ bc,
                         float* __restrict__ out) {
    __shared__ float sWc[256];
    __shared__ float sbc[16];
    int tid = threadIdx.x;
    sWc[tid] = Wc[tid];
    if (tid < 16) sbc[tid] = bc[tid];
    __syncthreads();

    const int b = blockIdx.x >> 8;
    const int i = (blockIdx.x & 255) + 1;   // padded row in [1,256]
    const int j = tid + 1;                  // padded col in [1,256]

    int khA[2], hoA[2], nh = 0;
    #pragma unroll
    for (int kh = 0; kh < 3; kh++) {
        int t = i - kh;
        if (t >= 0 && t <= 254 && !(t & 1)) { khA[nh] = kh; hoA[nh] = t >> 1; nh++; }
    }
    int kwA[2], woA[2], nw = 0;
    #pragma unroll
    for (int kw = 0; kw < 3; kw++) {
        int t = j - kw;
        if (t >= 0 && t <= 254 && !(t & 1)) { kwA[nw] = kw; woA[nw] = t >> 1; nw++; }
    }

    float nrm[16];
    #pragma unroll
    for (int c = 0; c < 16; c++) nrm[c] = 0.f;

    const float* gb = g_outp + (size_t)b * PP * LL;
    for (int a = 0; a < nh; a++)
        for (int d = 0; d < nw; d++) {
            const float* rec = gb + (size_t)(khA[a] * 3 + kwA[d]) * LL
                             + hoA[a] * 128 + woA[d];
            #pragma unroll
            for (int c = 0; c < 16; c++) nrm[c] += rec[(size_t)c * 9 * LL];
        }

    const float inv = 1.f / ((float)(nh * nw) + 1e-6f);
    #pragma unroll
    for (int c = 0; c < 16; c++) nrm[c] *= inv;

    float logit[16];
    #pragma unroll
    for (int o = 0; o < 16; o++) {
        float s = sbc[o];
        #pragma unroll
        for (int c = 0; c < 16; c++) s += sWc[o * 16 + c] * nrm[c];
        logit[o] = s;
    }
    float m = logit[0];
    #pragma unroll
    for (int o = 1; o < 16; o++) m = fmaxf(m, logit[o]);
    float e[16], sum = 0.f;
    #pragma unroll
    for (int o = 0; o < 16; o++) { e[o] = __expf(logit[o] - m); sum += e[o]; }
    const float rs = 1.f / sum;

    float* ob = out + (size_t)b * CC * HH * WWID + (size_t)(i - 1) * WWID + (j - 1);
    #pragma unroll
    for (int c = 0; c < 16; c++) ob[(size_t)c * HH * WWID] = nrm[c] * e[c] * rs;
}

// ---------------------------------------------------------------------------
extern "C" void kernel_launch(void* const* d_in, const int* in_sizes, int n_in,
                              void* d_out, int out_size) {
    const float* x  = (const float*)d_in[0];
    const float* W1 = (const float*)d_in[1];
    const float* b1 = (const float*)d_in[2];
    const float* W2 = (const float*)d_in[3];
    const float* b2 = (const float*)d_in[4];
    const float* Wc = (const float*)d_in[5];
    const float* bc = (const float*)d_in[6];
    float* out = (float*)d_out;

    cudaFuncSetAttribute(mlp_persist, cudaFuncAttributeMaxDynamicSharedMemorySize, SMEM_TOT);

    mlp_persist<<<NCTA, 256, SMEM_TOT>>>(x, W1, b1, W2, b2);
    fold_softmax_kernel<<<BB * 256, 256>>>(Wc, bc, out);
}

// round 9
// speedup vs baseline: 1.3660x; 1.1326x over previous
#include <cuda_runtime.h>
#include <cuda_fp16.h>
#include <cstdint>

#define BB   32
#define CC   16
#define HH   256
#define WWID 256
#define PP   144
#define HID  128
#define LL   16384
#define NT   8192      // tiles: 64 positions each
#define NCTA 152

// Scratch for out_p, layout (B, P, L) fp16 = 151 MB
__device__ __half g_outp[(size_t)BB * PP * LL];

// ---------------- smem byte offsets ----------------
#define OFF_B1H 0                  // 128 x 152 x 2B = 38912 (fp16 W1^T)
#define OFF_B2H 38912              // 144 x 136 x 2B = 39168 (fp16 W2^T)
#define OFF_AH  78080              // 64 x 152 x 2B = 19456 (A hi)
#define OFF_AL  97536              // 19456 (A lo, used by GEMM2 only)
#define OFF_b1  116992             // 512
#define OFF_b2  117504             // 576
#define SMEM_TOT 118144
#define AS1 152                    // 304B rows: 19*16B -> conflict-free ldmatrix
#define AS2 136                    // 272B rows: 17*16B
#define DA  19456                  // A hi->lo delta

// ---------------- helpers ----------------
__device__ __forceinline__ uint32_t smem_u32(const void* p) {
    uint32_t a;
    asm("{ .reg .u64 t; cvta.to.shared.u64 t, %1; cvt.u32.u64 %0, t; }" : "=r"(a) : "l"(p));
    return a;
}
__device__ __forceinline__ void ldsm4(uint32_t* r, uint32_t a) {
    asm volatile("ldmatrix.sync.aligned.m8n8.x4.shared.b16 {%0,%1,%2,%3}, [%4];"
                 : "=r"(r[0]), "=r"(r[1]), "=r"(r[2]), "=r"(r[3]) : "r"(a));
}
__device__ __forceinline__ void ldsm2(uint32_t* r, uint32_t a) {
    asm volatile("ldmatrix.sync.aligned.m8n8.x2.shared.b16 {%0,%1}, [%2];"
                 : "=r"(r[0]), "=r"(r[1]) : "r"(a));
}
__device__ __forceinline__ void mma_f16(float* d, const uint32_t* a, uint32_t b0, uint32_t b1) {
    asm volatile("mma.sync.aligned.m16n8k16.row.col.f32.f16.f16.f32 "
                 "{%0,%1,%2,%3}, {%4,%5,%6,%7}, {%8,%9}, {%0,%1,%2,%3};"
                 : "+f"(d[0]), "+f"(d[1]), "+f"(d[2]), "+f"(d[3])
                 : "r"(a[0]), "r"(a[1]), "r"(a[2]), "r"(a[3]), "r"(b0), "r"(b1));
}
__device__ __forceinline__ uint32_t packh(__half a, __half b) {
    return (uint32_t)*(uint16_t*)&a | ((uint32_t)*(uint16_t*)&b << 16);
}
__device__ __forceinline__ uint32_t pack_rn(float v0, float v1) {
    return packh(__float2half_rn(v0), __float2half_rn(v1));
}
// split v0,v1 -> packed hi f16x2 (return) and packed lo f16x2 (out param)
__device__ __forceinline__ uint32_t split_pack(float v0, float v1, uint32_t& lo) {
    __half h0 = __float2half_rn(v0), h1 = __float2half_rn(v1);
    __half l0 = __float2half_rn(v0 - __half2float(h0));
    __half l1 = __float2half_rn(v1 - __half2float(h1));
    lo = packh(l0, l1);
    return packh(h0, h1);
}
__device__ __forceinline__ int refl(int v, int n) {
    return (v < 0) ? -v : ((v >= n) ? 2 * n - 2 - v : v);
}

// ---------------------------------------------------------------------------
// Persistent MLP kernel. grid = NCTA, 256 threads (8 warps: 4m x 2n).
// GEMM1: pure fp16 (x rounded). GEMM2: 2-pass exact-H fp16 split.
// ---------------------------------------------------------------------------
__global__ __launch_bounds__(256, 1)
void mlp_persist(const float* __restrict__ x, const float* __restrict__ W1,
                 const float* __restrict__ b1, const float* __restrict__ W2,
                 const float* __restrict__ b2) {
    extern __shared__ char smem[];
    const uint32_t sb = smem_u32(smem);
    const int tid = threadIdx.x;
    const int wid = tid >> 5, lid = tid & 31;

    float* b1s = (float*)(smem + OFF_b1);
    float* b2s = (float*)(smem + OFF_b2);
    if (tid < 128) b1s[tid] = b1[tid];
    if (tid < 144) b2s[tid] = b2[tid];

    // ---- stage fp16 W1^T and W2^T ONCE ----
    #pragma unroll 4
    for (int i = 0; i < 72; i++) {
        int e = i * 256 + tid;               // e = k*128 + n
        int k = e >> 7, n = e & 127;
        __half h = __float2half_rn(__ldg(&W1[e]));
        *(uint16_t*)(smem + OFF_B1H + (uint32_t)(n * AS1 + k) * 2) = *(uint16_t*)&h;
    }
    #pragma unroll 4
    for (int i = 0; i < 72; i++) {
        int e = i * 256 + tid;               // e = k*144 + n
        int k = e / 144, n = e - k * 144;
        __half h = __float2half_rn(__ldg(&W2[e]));
        *(uint16_t*)(smem + OFF_B2H + (uint32_t)(n * AS2 + k) * 2) = *(uint16_t*)&h;
    }

    // warp tiling constants
    const int wm = (wid & 3) * 16;
    const int wn = wid >> 2;
    const int g = lid >> 3, r = lid & 7;
    const int khalf = (g >> 1) * 8;
    const int arow = wm + (g & 1) * 8 + r;
    const int g2 = (lid >> 3) & 1;

    // gather mapping: pos = tid>>2 (64 pos), quarter q = tid&3 -> 36 p-elems
    const int pos = tid >> 2;
    const int q   = tid & 3;
    const int pb  = q * 36;

    float xv[36];

    // ---- prefetch first tile ----
    {
        int t = blockIdx.x;
        int b = t >> 8, rem = t & 255, ho = rem >> 1, wo0 = (rem & 1) * 64;
        const float* xb = x + ((size_t)b * CC + q * 4) * (HH * WWID);
        int rw[3], cl[3];
        #pragma unroll
        for (int kk = 0; kk < 3; kk++) {
            rw[kk] = refl(2 * ho + kk - 1, HH) * WWID;
            cl[kk] = refl(2 * (wo0 + pos) + kk - 1, WWID);
        }
        #pragma unroll
        for (int ci = 0; ci < 4; ci++) {
            const float* xc = xb + ci * (HH * WWID);
            #pragma unroll
            for (int kh = 0; kh < 3; kh++)
                #pragma unroll
                for (int kw = 0; kw < 3; kw++)
                    xv[ci * 9 + kh * 3 + kw] = __ldg(&xc[rw[kh] + cl[kw]]);
        }
    }

    for (int t = blockIdx.x; t < NT; t += NCTA) {
        const int b = t >> 8, rem = t & 255, ho = rem >> 1, wo0 = (rem & 1) * 64;

        __syncthreads();   // prev GEMM2 done reading A buffer
        // ---- store A1 (fp16, hi only) ----
        #pragma unroll
        for (int i = 0; i < 18; i++) {
            uint32_t hi = pack_rn(xv[2 * i], xv[2 * i + 1]);
            uint32_t off = (uint32_t)(pos * AS1 + pb + 2 * i) * 2;
            *(uint32_t*)(smem + OFF_AH + off) = hi;
        }
        __syncthreads();

        // ---- GEMM1: D1[64 x 128], warp covers 16m x 64n, single pass ----
        float d1[8][4];
        #pragma unroll
        for (int nj = 0; nj < 8; nj++)
            #pragma unroll
            for (int p = 0; p < 4; p++) d1[nj][p] = 0.f;
        {
            uint32_t pA = sb + OFF_AH + (uint32_t)(arow * AS1 + khalf) * 2;
            uint32_t pB[4];
            #pragma unroll
            for (int np = 0; np < 4; np++)
                pB[np] = sb + OFF_B1H + (uint32_t)((wn * 64 + np * 16 + (g & 1) * 8 + r) * AS1 + khalf) * 2;

            uint32_t a[4], bA[4][4];
            #pragma unroll
            for (int ks = 0; ks < 9; ks++) {
                const uint32_t ko = ks * 32;
                ldsm4(a, pA + ko);
                #pragma unroll
                for (int np = 0; np < 4; np++) ldsm4(bA[np], pB[np] + ko);
                #pragma unroll
                for (int np = 0; np < 4; np++) {
                    mma_f16(d1[np * 2],     a, bA[np][0], bA[np][2]);
                    mma_f16(d1[np * 2 + 1], a, bA[np][1], bA[np][3]);
                }
            }
        }
        __syncthreads();   // all warps done reading A1

        // ---- epi1: relu(D1+b1) split -> A2 hi/lo (stride AS2) ----
        {
            const int r0 = lid >> 2;
            const int c0 = (lid & 3) * 2;
            #pragma unroll
            for (int nj = 0; nj < 8; nj++) {
                const int col = wn * 64 + nj * 8 + c0;
                const float bb0 = b1s[col], bb1 = b1s[col + 1];
                float v0 = d1[nj][0] + bb0; v0 = v0 > 0.f ? v0 : 0.f;
                float v1 = d1[nj][1] + bb1; v1 = v1 > 0.f ? v1 : 0.f;
                float v2 = d1[nj][2] + bb0; v2 = v2 > 0.f ? v2 : 0.f;
                float v3 = d1[nj][3] + bb1; v3 = v3 > 0.f ? v3 : 0.f;
                uint32_t lo, hi;
                uint32_t offA = (uint32_t)((wm + r0) * AS2 + col) * 2;
                hi = split_pack(v0, v1, lo);
                *(uint32_t*)(smem + OFF_AH + offA) = hi;
                *(uint32_t*)(smem + OFF_AL + offA) = lo;
                uint32_t offB = (uint32_t)((wm + r0 + 8) * AS2 + col) * 2;
                hi = split_pack(v2, v3, lo);
                *(uint32_t*)(smem + OFF_AH + offB) = hi;
                *(uint32_t*)(smem + OFF_AL + offB) = lo;
            }
        }

        // ---- prefetch next tile (overlaps GEMM2) ----
        {
            int tn = t + NCTA;
            if (tn < NT) {
                int bn = tn >> 8, remn = tn & 255, hon = remn >> 1, wo0n = (remn & 1) * 64;
                const float* xb = x + ((size_t)bn * CC + q * 4) * (HH * WWID);
                int rw[3], cl[3];
                #pragma unroll
                for (int kk = 0; kk < 3; kk++) {
                    rw[kk] = refl(2 * hon + kk - 1, HH) * WWID;
                    cl[kk] = refl(2 * (wo0n + pos) + kk - 1, WWID);
                }
                #pragma unroll
                for (int ci = 0; ci < 4; ci++) {
                    const float* xc = xb + ci * (HH * WWID);
                    #pragma unroll
                    for (int kh = 0; kh < 3; kh++)
                        #pragma unroll
                        for (int kw = 0; kw < 3; kw++)
                            xv[ci * 9 + kh * 3 + kw] = __ldg(&xc[rw[kh] + cl[kw]]);
                }
            }
        }
        __syncthreads();   // A2 visible

        // ---- GEMM2: D2[64 x 144], warp covers 16m x 72n, 2 A-passes ----
        float d2[9][4];
        #pragma unroll
        for (int nj = 0; nj < 9; nj++)
            #pragma unroll
            for (int p = 0; p < 4; p++) d2[nj][p] = 0.f;
        {
            uint32_t pA = sb + OFF_AH + (uint32_t)(arow * AS2 + khalf) * 2;
            uint32_t pB[4], pS;
            #pragma unroll
            for (int np = 0; np < 4; np++)
                pB[np] = sb + OFF_B2H + (uint32_t)((wn * 72 + np * 16 + (g & 1) * 8 + r) * AS2 + khalf) * 2;
            pS = sb + OFF_B2H + (uint32_t)((wn * 72 + 64 + r) * AS2 + g2 * 8) * 2;

            uint32_t a[4], bA[4][4], sA[2];
            #pragma unroll
            for (int ks = 0; ks < 8; ks++) {
                const uint32_t ko = ks * 32;
                ldsm4(a, pA + ko);
                #pragma unroll
                for (int np = 0; np < 4; np++) ldsm4(bA[np], pB[np] + ko);
                ldsm2(sA, pS + ko);
                #pragma unroll
                for (int np = 0; np < 4; np++) {
                    mma_f16(d2[np * 2],     a, bA[np][0], bA[np][2]);
                    mma_f16(d2[np * 2 + 1], a, bA[np][1], bA[np][3]);
                }
                mma_f16(d2[8], a, sA[0], sA[1]);
                ldsm4(a, pA + DA + ko);
                #pragma unroll
                for (int np = 0; np < 4; np++) {
                    mma_f16(d2[np * 2],     a, bA[np][0], bA[np][2]);
                    mma_f16(d2[np * 2 + 1], a, bA[np][1], bA[np][3]);
                }
                mma_f16(d2[8], a, sA[0], sA[1]);
            }
        }

        // ---- epi2: D2 + b2 -> g_outp[b][col][pos] (fp16, coalesced runs) ----
        {
            const int r0 = lid >> 2;
            const int c0 = (lid & 3) * 2;
            __half* ob = g_outp + (size_t)b * PP * LL + (size_t)ho * 128 + wo0;
            const int posA = wm + r0;
            const int posB = posA + 8;
            #pragma unroll
            for (int nj = 0; nj < 9; nj++) {
                const int col = wn * 72 + nj * 8 + c0;
                const float bb0 = b2s[col], bb1 = b2s[col + 1];
                __half* c0p = ob + (size_t)col * LL;
                __half* c1p = c0p + LL;
                c0p[posA] = __float2half_rn(d2[nj][0] + bb0);
                c1p[posA] = __float2half_rn(d2[nj][1] + bb1);
                c0p[posB] = __float2half_rn(d2[nj][2] + bb0);
                c1p[posB] = __float2half_rn(d2[nj][3] + bb1);
            }
        }
    }
}

// ---------------------------------------------------------------------------
// Kernel B: gather-fold + normalize + channel mix + softmax + modulate
// ---------------------------------------------------------------------------
__global__ __launch_bounds__(256)
void fold_softmax_kernel(const float* __restrict__ Wc, const float* __restrict__ bc,
                         float* __restrict__ out) {
    __shared__ float sWc[256];
    __shared__ float sbc[16];
    int tid = threadIdx.x;
    sWc[tid] = Wc[tid];
    if (tid < 16) sbc[tid] = bc[tid];
    __syncthreads();

    const int b = blockIdx.x >> 8;
    const int i = (blockIdx.x & 255) + 1;   // padded row in [1,256]
    const int j = tid + 1;                  // padded col in [1,256]

    int khA[2], hoA[2], nh = 0;
    #pragma unroll
    for (int kh = 0; kh < 3; kh++) {
        int t = i - kh;
        if (t >= 0 && t <= 254 && !(t & 1)) { khA[nh] = kh; hoA[nh] = t >> 1; nh++; }
    }
    int kwA[2], woA[2], nw = 0;
    #pragma unroll
    for (int kw = 0; kw < 3; kw++) {
        int t = j - kw;
        if (t >= 0 && t <= 254 && !(t & 1)) { kwA[nw] = kw; woA[nw] = t >> 1; nw++; }
    }

    float nrm[16];
    #pragma unroll
    for (int c = 0; c < 16; c++) nrm[c] = 0.f;

    const __half* gb = g_outp + (size_t)b * PP * LL;
    for (int a = 0; a < nh; a++)
        for (int d = 0; d < nw; d++) {
            const __half* rec = gb + (size_t)(khA[a] * 3 + kwA[d]) * LL
                              + hoA[a] * 128 + woA[d];
            #pragma unroll
            for (int c = 0; c < 16; c++) nrm[c] += __half2float(rec[(size_t)c * 9 * LL]);
        }

    const float inv = 1.f / ((float)(nh * nw) + 1e-6f);
    #pragma unroll
    for (int c = 0; c < 16; c++) nrm[c] *= inv;

    float logit[16];
    #pragma unroll
    for (int o = 0; o < 16; o++) {
        float s = sbc[o];
        #pragma unroll
        for (int c = 0; c < 16; c++) s += sWc[o * 16 + c] * nrm[c];
        logit[o] = s;
    }
    float m = logit[0];
    #pragma unroll
    for (int o = 1; o < 16; o++) m = fmaxf(m, logit[o]);
    float e[16], sum = 0.f;
    #pragma unroll
    for (int o = 0; o < 16; o++) { e[o] = __expf(logit[o] - m); sum += e[o]; }
    const float rs = 1.f / sum;

    float* ob = out + (size_t)b * CC * HH * WWID + (size_t)(i - 1) * WWID + (j - 1);
    #pragma unroll
    for (int c = 0; c < 16; c++) ob[(size_t)c * HH * WWID] = nrm[c] * e[c] * rs;
}

// ---------------------------------------------------------------------------
extern "C" void kernel_launch(void* const* d_in, const int* in_sizes, int n_in,
                              void* d_out, int out_size) {
    const float* x  = (const float*)d_in[0];
    const float* W1 = (const float*)d_in[1];
    const float* b1 = (const float*)d_in[2];
    const float* W2 = (const float*)d_in[3];
    const float* b2 = (const float*)d_in[4];
    const float* Wc = (const float*)d_in[5];
    const float* bc = (const float*)d_in[6];
    float* out = (float*)d_out;

    cudaFuncSetAttribute(mlp_persist, cudaFuncAttributeMaxDynamicSharedMemorySize, SMEM_TOT);

    mlp_persist<<<NCTA, 256, SMEM_TOT>>>(x, W1, b1, W2, b2);
    fold_softmax_kernel<<<BB * 256, 256>>>(Wc, bc, out);
}

// round 10
// speedup vs baseline: 1.4681x; 1.0748x over previous
#include <cuda_runtime.h>
#include <cuda_fp16.h>
#include <cstdint>

#define BB   32
#define CC   16
#define HH   256
#define WWID 256
#define PP   144
#define HID  128
#define LL   16384
#define NT   8192      // tiles: 64 positions each
#define NCTA 152

// Scratch for out_p, layout (B, P, L) fp16 = 151 MB
__device__ __half g_outp[(size_t)BB * PP * LL];

// ---------------- smem byte offsets ----------------
#define OFF_B1H 0                  // 128 x 152 x 2B = 38912 (fp16 W1^T)
#define OFF_B2H 38912              // 144 x 136 x 2B = 39168 (fp16 W2^T)
#define OFF_AH  78080              // 64 x 152 x 2B = 19456 (A, fp16)
#define OFF_b1  97536              // 512
#define OFF_b2  98048              // 576
#define SMEM_TOT 98624
#define AS1 152                    // 304B rows: 19*16B -> conflict-free ldmatrix
#define AS2 136                    // 272B rows: 17*16B

// ---------------- helpers ----------------
__device__ __forceinline__ uint32_t smem_u32(const void* p) {
    uint32_t a;
    asm("{ .reg .u64 t; cvta.to.shared.u64 t, %1; cvt.u32.u64 %0, t; }" : "=r"(a) : "l"(p));
    return a;
}
__device__ __forceinline__ void ldsm4(uint32_t* r, uint32_t a) {
    asm volatile("ldmatrix.sync.aligned.m8n8.x4.shared.b16 {%0,%1,%2,%3}, [%4];"
                 : "=r"(r[0]), "=r"(r[1]), "=r"(r[2]), "=r"(r[3]) : "r"(a));
}
__device__ __forceinline__ void ldsm2(uint32_t* r, uint32_t a) {
    asm volatile("ldmatrix.sync.aligned.m8n8.x2.shared.b16 {%0,%1}, [%2];"
                 : "=r"(r[0]), "=r"(r[1]) : "r"(a));
}
__device__ __forceinline__ void mma_f16(float* d, const uint32_t* a, uint32_t b0, uint32_t b1) {
    asm volatile("mma.sync.aligned.m16n8k16.row.col.f32.f16.f16.f32 "
                 "{%0,%1,%2,%3}, {%4,%5,%6,%7}, {%8,%9}, {%0,%1,%2,%3};"
                 : "+f"(d[0]), "+f"(d[1]), "+f"(d[2]), "+f"(d[3])
                 : "r"(a[0]), "r"(a[1]), "r"(a[2]), "r"(a[3]), "r"(b0), "r"(b1));
}
__device__ __forceinline__ uint32_t packh(__half a, __half b) {
    return (uint32_t)*(uint16_t*)&a | ((uint32_t)*(uint16_t*)&b << 16);
}
__device__ __forceinline__ uint32_t pack_rn(float v0, float v1) {
    return packh(__float2half_rn(v0), __float2half_rn(v1));
}
__device__ __forceinline__ int refl(int v, int n) {
    return (v < 0) ? -v : ((v >= n) ? 2 * n - 2 - v : v);
}

// ---------------------------------------------------------------------------
// Persistent MLP kernel. grid = NCTA, 256 threads (8 warps: 4m x 2n).
// Both GEMMs single-pass fp16 (fp32 accumulate). Tile = 64 positions.
// ---------------------------------------------------------------------------
__global__ __launch_bounds__(256, 1)
void mlp_persist(const float* __restrict__ x, const float* __restrict__ W1,
                 const float* __restrict__ b1, const float* __restrict__ W2,
                 const float* __restrict__ b2) {
    extern __shared__ char smem[];
    const uint32_t sb = smem_u32(smem);
    const int tid = threadIdx.x;
    const int wid = tid >> 5, lid = tid & 31;

    float* b1s = (float*)(smem + OFF_b1);
    float* b2s = (float*)(smem + OFF_b2);
    if (tid < 128) b1s[tid] = b1[tid];
    if (tid < 144) b2s[tid] = b2[tid];

    // ---- stage fp16 W1^T and W2^T ONCE ----
    #pragma unroll 4
    for (int i = 0; i < 72; i++) {
        int e = i * 256 + tid;               // e = k*128 + n
        int k = e >> 7, n = e & 127;
        __half h = __float2half_rn(__ldg(&W1[e]));
        *(uint16_t*)(smem + OFF_B1H + (uint32_t)(n * AS1 + k) * 2) = *(uint16_t*)&h;
    }
    #pragma unroll 4
    for (int i = 0; i < 72; i++) {
        int e = i * 256 + tid;               // e = k*144 + n
        int k = e / 144, n = e - k * 144;
        __half h = __float2half_rn(__ldg(&W2[e]));
        *(uint16_t*)(smem + OFF_B2H + (uint32_t)(n * AS2 + k) * 2) = *(uint16_t*)&h;
    }

    // warp tiling constants
    const int wm = (wid & 3) * 16;
    const int wn = wid >> 2;
    const int g = lid >> 3, r = lid & 7;
    const int khalf = (g >> 1) * 8;
    const int arow = wm + (g & 1) * 8 + r;
    const int g2 = (lid >> 3) & 1;

    // gather mapping: pos = tid>>2 (64 pos), quarter q = tid&3 -> 36 p-elems
    const int pos = tid >> 2;
    const int q   = tid & 3;
    const int pb  = q * 36;

    float xv[36];

    // ---- prefetch first tile ----
    {
        int t = blockIdx.x;
        int b = t >> 8, rem = t & 255, ho = rem >> 1, wo0 = (rem & 1) * 64;
        const float* xb = x + ((size_t)b * CC + q * 4) * (HH * WWID);
        int rw[3], cl[3];
        #pragma unroll
        for (int kk = 0; kk < 3; kk++) {
            rw[kk] = refl(2 * ho + kk - 1, HH) * WWID;
            cl[kk] = refl(2 * (wo0 + pos) + kk - 1, WWID);
        }
        #pragma unroll
        for (int ci = 0; ci < 4; ci++) {
            const float* xc = xb + ci * (HH * WWID);
            #pragma unroll
            for (int kh = 0; kh < 3; kh++)
                #pragma unroll
                for (int kw = 0; kw < 3; kw++)
                    xv[ci * 9 + kh * 3 + kw] = __ldg(&xc[rw[kh] + cl[kw]]);
        }
    }

    for (int t = blockIdx.x; t < NT; t += NCTA) {
        const int b = t >> 8, rem = t & 255, ho = rem >> 1, wo0 = (rem & 1) * 64;

        __syncthreads();   // prev GEMM2 done reading A buffer
        // ---- store A1 (fp16) ----
        #pragma unroll
        for (int i = 0; i < 18; i++) {
            uint32_t hi = pack_rn(xv[2 * i], xv[2 * i + 1]);
            uint32_t off = (uint32_t)(pos * AS1 + pb + 2 * i) * 2;
            *(uint32_t*)(smem + OFF_AH + off) = hi;
        }
        __syncthreads();

        // ---- GEMM1: D1[64 x 128], warp covers 16m x 64n ----
        float d1[8][4];
        #pragma unroll
        for (int nj = 0; nj < 8; nj++)
            #pragma unroll
            for (int p = 0; p < 4; p++) d1[nj][p] = 0.f;
        {
            uint32_t pA = sb + OFF_AH + (uint32_t)(arow * AS1 + khalf) * 2;
            uint32_t pB[4];
            #pragma unroll
            for (int np = 0; np < 4; np++)
                pB[np] = sb + OFF_B1H + (uint32_t)((wn * 64 + np * 16 + (g & 1) * 8 + r) * AS1 + khalf) * 2;

            uint32_t a[4], bA[4][4];
            #pragma unroll
            for (int ks = 0; ks < 9; ks++) {
                const uint32_t ko = ks * 32;
                ldsm4(a, pA + ko);
                #pragma unroll
                for (int np = 0; np < 4; np++) ldsm4(bA[np], pB[np] + ko);
                #pragma unroll
                for (int np = 0; np < 4; np++) {
                    mma_f16(d1[np * 2],     a, bA[np][0], bA[np][2]);
                    mma_f16(d1[np * 2 + 1], a, bA[np][1], bA[np][3]);
                }
            }
        }
        __syncthreads();   // all warps done reading A1

        // ---- epi1: relu(D1+b1) fp16 -> A2 (stride AS2) ----
        {
            const int r0 = lid >> 2;
            const int c0 = (lid & 3) * 2;
            #pragma unroll
            for (int nj = 0; nj < 8; nj++) {
                const int col = wn * 64 + nj * 8 + c0;
                const float bb0 = b1s[col], bb1 = b1s[col + 1];
                float v0 = d1[nj][0] + bb0; v0 = v0 > 0.f ? v0 : 0.f;
                float v1 = d1[nj][1] + bb1; v1 = v1 > 0.f ? v1 : 0.f;
                float v2 = d1[nj][2] + bb0; v2 = v2 > 0.f ? v2 : 0.f;
                float v3 = d1[nj][3] + bb1; v3 = v3 > 0.f ? v3 : 0.f;
                *(uint32_t*)(smem + OFF_AH + (uint32_t)((wm + r0) * AS2 + col) * 2)     = pack_rn(v0, v1);
                *(uint32_t*)(smem + OFF_AH + (uint32_t)((wm + r0 + 8) * AS2 + col) * 2) = pack_rn(v2, v3);
            }
        }

        // ---- prefetch next tile (overlaps GEMM2) ----
        {
            int tn = t + NCTA;
            if (tn < NT) {
                int bn = tn >> 8, remn = tn & 255, hon = remn >> 1, wo0n = (remn & 1) * 64;
                const float* xb = x + ((size_t)bn * CC + q * 4) * (HH * WWID);
                int rw[3], cl[3];
                #pragma unroll
                for (int kk = 0; kk < 3; kk++) {
                    rw[kk] = refl(2 * hon + kk - 1, HH) * WWID;
                    cl[kk] = refl(2 * (wo0n + pos) + kk - 1, WWID);
                }
                #pragma unroll
                for (int ci = 0; ci < 4; ci++) {
                    const float* xc = xb + ci * (HH * WWID);
                    #pragma unroll
                    for (int kh = 0; kh < 3; kh++)
                        #pragma unroll
                        for (int kw = 0; kw < 3; kw++)
                            xv[ci * 9 + kh * 3 + kw] = __ldg(&xc[rw[kh] + cl[kw]]);
                }
            }
        }
        __syncthreads();   // A2 visible

        // ---- GEMM2: D2[64 x 144], warp covers 16m x 72n ----
        float d2[9][4];
        #pragma unroll
        for (int nj = 0; nj < 9; nj++)
            #pragma unroll
            for (int p = 0; p < 4; p++) d2[nj][p] = 0.f;
        {
            uint32_t pA = sb + OFF_AH + (uint32_t)(arow * AS2 + khalf) * 2;
            uint32_t pB[4], pS;
            #pragma unroll
            for (int np = 0; np < 4; np++)
                pB[np] = sb + OFF_B2H + (uint32_t)((wn * 72 + np * 16 + (g & 1) * 8 + r) * AS2 + khalf) * 2;
            pS = sb + OFF_B2H + (uint32_t)((wn * 72 + 64 + r) * AS2 + g2 * 8) * 2;

            uint32_t a[4], bA[4][4], sA[2];
            #pragma unroll
            for (int ks = 0; ks < 8; ks++) {
                const uint32_t ko = ks * 32;
                ldsm4(a, pA + ko);
                #pragma unroll
                for (int np = 0; np < 4; np++) ldsm4(bA[np], pB[np] + ko);
                ldsm2(sA, pS + ko);
                #pragma unroll
                for (int np = 0; np < 4; np++) {
                    mma_f16(d2[np * 2],     a, bA[np][0], bA[np][2]);
                    mma_f16(d2[np * 2 + 1], a, bA[np][1], bA[np][3]);
                }
                mma_f16(d2[8], a, sA[0], sA[1]);
            }
        }

        // ---- epi2: D2 + b2 -> g_outp[b][col][pos] (fp16, coalesced runs) ----
        {
            const int r0 = lid >> 2;
            const int c0 = (lid & 3) * 2;
            __half* ob = g_outp + (size_t)b * PP * LL + (size_t)ho * 128 + wo0;
            const int posA = wm + r0;
            const int posB = posA + 8;
            #pragma unroll
            for (int nj = 0; nj < 9; nj++) {
                const int col = wn * 72 + nj * 8 + c0;
                const float bb0 = b2s[col], bb1 = b2s[col + 1];
                __half* c0p = ob + (size_t)col * LL;
                __half* c1p = c0p + LL;
                c0p[posA] = __float2half_rn(d2[nj][0] + bb0);
                c1p[posA] = __float2half_rn(d2[nj][1] + bb1);
                c0p[posB] = __float2half_rn(d2[nj][2] + bb0);
                c1p[posB] = __float2half_rn(d2[nj][3] + bb1);
            }
        }
    }
}

// ---------------------------------------------------------------------------
// Kernel B: branchless 4-contributor gather-fold + normalize + channel mix +
// softmax + modulate. All 64 loads unconditional -> full MLP.
// ---------------------------------------------------------------------------
__global__ __launch_bounds__(256)
void fold_softmax_kernel(const float* __restrict__ Wc, const float* __restrict__ bc,
                         float* __restrict__ out) {
    __shared__ float sWc[256];
    __shared__ float sbc[16];
    int tid = threadIdx.x;
    sWc[tid] = Wc[tid];
    if (tid < 16) sbc[tid] = bc[tid];
    __syncthreads();

    const int b = blockIdx.x >> 8;
    const int i = (blockIdx.x & 255) + 1;   // padded row in [1,256]
    const int j = tid + 1;                  // padded col in [1,256]

    // h-axis contributors (kh, ho, weight)
    int kh0, kh1, ho0, ho1; float wh0, wh1;
    if (i & 1) { kh0 = 1; ho0 = (i - 1) >> 1; wh0 = 1.f; kh1 = 1; ho1 = ho0; wh1 = 0.f; }
    else {
        kh0 = 0; ho0 = i >> 1; wh0 = (ho0 <= 127) ? 1.f : 0.f; if (ho0 > 127) ho0 = 127;
        kh1 = 2; ho1 = (i - 2) >> 1; wh1 = 1.f;
    }
    // w-axis contributors
    int kw0, kw1, wo0, wo1; float ww0, ww1;
    if (j & 1) { kw0 = 1; wo0 = (j - 1) >> 1; ww0 = 1.f; kw1 = 1; wo1 = wo0; ww1 = 0.f; }
    else {
        kw0 = 0; wo0 = j >> 1; ww0 = (wo0 <= 127) ? 1.f : 0.f; if (wo0 > 127) wo0 = 127;
        kw1 = 2; wo1 = (j - 2) >> 1; ww1 = 1.f;
    }

    const __half* gb = g_outp + (size_t)b * PP * LL;
    const __half* r00 = gb + (size_t)(kh0 * 3 + kw0) * LL + ho0 * 128 + wo0;
    const __half* r01 = gb + (size_t)(kh0 * 3 + kw1) * LL + ho0 * 128 + wo1;
    const __half* r10 = gb + (size_t)(kh1 * 3 + kw0) * LL + ho1 * 128 + wo0;
    const __half* r11 = gb + (size_t)(kh1 * 3 + kw1) * LL + ho1 * 128 + wo1;
    const float w00 = wh0 * ww0, w01 = wh0 * ww1, w10 = wh1 * ww0, w11 = wh1 * ww1;

    float nrm[16];
    #pragma unroll
    for (int c = 0; c < 16; c++) {
        const size_t o = (size_t)c * 9 * LL;
        nrm[c] = w00 * __half2float(__ldg(r00 + o))
               + w01 * __half2float(__ldg(r01 + o))
               + w10 * __half2float(__ldg(r10 + o))
               + w11 * __half2float(__ldg(r11 + o));
    }

    const float inv = 1.f / ((wh0 + wh1) * (ww0 + ww1) + 1e-6f);
    #pragma unroll
    for (int c = 0; c < 16; c++) nrm[c] *= inv;

    float logit[16];
    #pragma unroll
    for (int o = 0; o < 16; o++) {
        float s = sbc[o];
        #pragma unroll
        for (int c = 0; c < 16; c++) s += sWc[o * 16 + c] * nrm[c];
        logit[o] = s;
    }
    float m = logit[0];
    #pragma unroll
    for (int o = 1; o < 16; o++) m = fmaxf(m, logit[o]);
    float e[16], sum = 0.f;
    #pragma unroll
    for (int o = 0; o < 16; o++) { e[o] = __expf(logit[o] - m); sum += e[o]; }
    const float rs = 1.f / sum;

    float* ob = out + (size_t)b * CC * HH * WWID + (size_t)(i - 1) * WWID + (j - 1);
    #pragma unroll
    for (int c = 0; c < 16; c++) ob[(size_t)c * HH * WWID] = nrm[c] * e[c] * rs;
}

// ---------------------------------------------------------------------------
extern "C" void kernel_launch(void* const* d_in, const int* in_sizes, int n_in,
                              void* d_out, int out_size) {
    const float* x  = (const float*)d_in[0];
    const float* W1 = (const float*)d_in[1];
    const float* b1 = (const float*)d_in[2];
    const float* W2 = (const float*)d_in[3];
    const float* b2 = (const float*)d_in[4];
    const float* Wc = (const float*)d_in[5];
    const float* bc = (const float*)d_in[6];
    float* out = (float*)d_out;

    cudaFuncSetAttribute(mlp_persist, cudaFuncAttributeMaxDynamicSharedMemorySize, SMEM_TOT);

    mlp_persist<<<NCTA, 256, SMEM_TOT>>>(x, W1, b1, W2, b2);
    fold_softmax_kernel<<<BB * 256, 256>>>(Wc, bc, out);
}

// round 11
// speedup vs baseline: 1.6360x; 1.1144x over previous
#include <cuda_runtime.h>
#include <cuda_fp16.h>
#include <cstdint>

#define BB   32
#define CC   16
#define HH   256
#define WWID 256
#define PP   144
#define HID  128
#define LL   16384
#define NT   8192      // tiles: 64 positions each
#define NCTA 152

// Scratch for out_p, paired-column layout (B, 72, L, 2) fp16 = 151 MB
// element (b, p, l) lives at b*PP*LL + (p&~1)*LL + l*2 + (p&1)
__device__ __half g_outp[(size_t)BB * PP * LL];

// ---------------- smem byte offsets ----------------
#define OFF_B1H 0                  // 128 x 152 x 2B = 38912 (fp16 W1^T)
#define OFF_B2H 38912              // 144 x 136 x 2B = 39168 (fp16 W2^T)
#define OFF_A1  78080              // 64 x 152 x 2B = 19456 (A1, fp16)
#define OFF_A2  97536              // 64 x 136 x 2B = 17408 (A2, fp16)
#define OFF_b1  114944             // 512
#define OFF_b2  115456             // 576
#define SMEM_TOT 116032
#define AS1 152                    // 304B rows: 19*16B -> conflict-free ldmatrix
#define AS2 136                    // 272B rows: 17*16B

// ---------------- helpers ----------------
__device__ __forceinline__ uint32_t smem_u32(const void* p) {
    uint32_t a;
    asm("{ .reg .u64 t; cvta.to.shared.u64 t, %1; cvt.u32.u64 %0, t; }" : "=r"(a) : "l"(p));
    return a;
}
__device__ __forceinline__ void ldsm4(uint32_t* r, uint32_t a) {
    asm volatile("ldmatrix.sync.aligned.m8n8.x4.shared.b16 {%0,%1,%2,%3}, [%4];"
                 : "=r"(r[0]), "=r"(r[1]), "=r"(r[2]), "=r"(r[3]) : "r"(a));
}
__device__ __forceinline__ void ldsm2(uint32_t* r, uint32_t a) {
    asm volatile("ldmatrix.sync.aligned.m8n8.x2.shared.b16 {%0,%1}, [%2];"
                 : "=r"(r[0]), "=r"(r[1]) : "r"(a));
}
__device__ __forceinline__ void mma_f16(float* d, const uint32_t* a, uint32_t b0, uint32_t b1) {
    asm volatile("mma.sync.aligned.m16n8k16.row.col.f32.f16.f16.f32 "
                 "{%0,%1,%2,%3}, {%4,%5,%6,%7}, {%8,%9}, {%0,%1,%2,%3};"
                 : "+f"(d[0]), "+f"(d[1]), "+f"(d[2]), "+f"(d[3])
                 : "r"(a[0]), "r"(a[1]), "r"(a[2]), "r"(a[3]), "r"(b0), "r"(b1));
}
// single-instruction packed f32x2 -> f16x2 convert
__device__ __forceinline__ uint32_t pack_rn(float v0, float v1) {
    __half2 h = __float22half2_rn(make_float2(v0, v1));
    return *(uint32_t*)&h;
}
__device__ __forceinline__ int refl(int v, int n) {
    return (v < 0) ? -v : ((v >= n) ? 2 * n - 2 - v : v);
}

// ---------------------------------------------------------------------------
// Persistent MLP kernel. grid = NCTA, 256 threads (8 warps: 4m x 2n).
// Both GEMMs single-pass fp16 (fp32 accumulate). Tile = 64 positions.
// Separate A1/A2 buffers -> 2 syncthreads per tile.
// ---------------------------------------------------------------------------
__global__ __launch_bounds__(256, 1)
void mlp_persist(const float* __restrict__ x, const float* __restrict__ W1,
                 const float* __restrict__ b1, const float* __restrict__ W2,
                 const float* __restrict__ b2) {
    extern __shared__ char smem[];
    const uint32_t sb = smem_u32(smem);
    const int tid = threadIdx.x;
    const int wid = tid >> 5, lid = tid & 31;

    float* b1s = (float*)(smem + OFF_b1);
    float* b2s = (float*)(smem + OFF_b2);
    if (tid < 128) b1s[tid] = b1[tid];
    if (tid < 144) b2s[tid] = b2[tid];

    // ---- stage fp16 W1^T and W2^T ONCE ----
    #pragma unroll 4
    for (int i = 0; i < 72; i++) {
        int e = i * 256 + tid;               // e = k*128 + n
        int k = e >> 7, n = e & 127;
        __half h = __float2half_rn(__ldg(&W1[e]));
        *(uint16_t*)(smem + OFF_B1H + (uint32_t)(n * AS1 + k) * 2) = *(uint16_t*)&h;
    }
    #pragma unroll 4
    for (int i = 0; i < 72; i++) {
        int e = i * 256 + tid;               // e = k*144 + n
        int k = e / 144, n = e - k * 144;
        __half h = __float2half_rn(__ldg(&W2[e]));
        *(uint16_t*)(smem + OFF_B2H + (uint32_t)(n * AS2 + k) * 2) = *(uint16_t*)&h;
    }

    // warp tiling constants
    const int wm = (wid & 3) * 16;
    const int wn = wid >> 2;
    const int g = lid >> 3, r = lid & 7;
    const int khalf = (g >> 1) * 8;
    const int arow = wm + (g & 1) * 8 + r;
    const int g2 = (lid >> 3) & 1;

    // gather mapping: pos = tid>>2 (64 pos), quarter q = tid&3 -> 36 p-elems
    const int pos = tid >> 2;
    const int q   = tid & 3;
    const int pb  = q * 36;

    float xv[36];

    // ---- prefetch first tile ----
    {
        int t = blockIdx.x;
        int b = t >> 8, rem = t & 255, ho = rem >> 1, wo0 = (rem & 1) * 64;
        const float* xb = x + ((size_t)b * CC + q * 4) * (HH * WWID);
        int rw[3], cl[3];
        #pragma unroll
        for (int kk = 0; kk < 3; kk++) {
            rw[kk] = refl(2 * ho + kk - 1, HH) * WWID;
            cl[kk] = refl(2 * (wo0 + pos) + kk - 1, WWID);
        }
        #pragma unroll
        for (int ci = 0; ci < 4; ci++) {
            const float* xc = xb + ci * (HH * WWID);
            #pragma unroll
            for (int kh = 0; kh < 3; kh++)
                #pragma unroll
                for (int kw = 0; kw < 3; kw++)
                    xv[ci * 9 + kh * 3 + kw] = __ldg(&xc[rw[kh] + cl[kw]]);
        }
    }

    for (int t = blockIdx.x; t < NT; t += NCTA) {
        const int b = t >> 8, rem = t & 255, ho = rem >> 1, wo0 = (rem & 1) * 64;

        // ---- store A1 (fp16). Safe: last A1 readers finished before the
        //      pre-GEMM2 sync of the previous tile. ----
        #pragma unroll
        for (int i = 0; i < 18; i++) {
            uint32_t hi = pack_rn(xv[2 * i], xv[2 * i + 1]);
            uint32_t off = (uint32_t)(pos * AS1 + pb + 2 * i) * 2;
            *(uint32_t*)(smem + OFF_A1 + off) = hi;
        }
        __syncthreads();   // A1 complete; also orders prev GEMM2 before epi1

        // ---- GEMM1: D1[64 x 128], warp covers 16m x 64n ----
        float d1[8][4];
        #pragma unroll
        for (int nj = 0; nj < 8; nj++)
            #pragma unroll
            for (int p = 0; p < 4; p++) d1[nj][p] = 0.f;
        {
            uint32_t pA = sb + OFF_A1 + (uint32_t)(arow * AS1 + khalf) * 2;
            uint32_t pB[4];
            #pragma unroll
            for (int np = 0; np < 4; np++)
                pB[np] = sb + OFF_B1H + (uint32_t)((wn * 64 + np * 16 + (g & 1) * 8 + r) * AS1 + khalf) * 2;

            uint32_t a[4], bA[4][4];
            #pragma unroll
            for (int ks = 0; ks < 9; ks++) {
                const uint32_t ko = ks * 32;
                ldsm4(a, pA + ko);
                #pragma unroll
                for (int np = 0; np < 4; np++) ldsm4(bA[np], pB[np] + ko);
                #pragma unroll
                for (int np = 0; np < 4; np++) {
                    mma_f16(d1[np * 2],     a, bA[np][0], bA[np][2]);
                    mma_f16(d1[np * 2 + 1], a, bA[np][1], bA[np][3]);
                }
            }
        }

        // ---- epi1: relu(D1+b1) fp16 -> A2 (separate buffer, no sync needed) ----
        {
            const int r0 = lid >> 2;
            const int c0 = (lid & 3) * 2;
            #pragma unroll
            for (int nj = 0; nj < 8; nj++) {
                const int col = wn * 64 + nj * 8 + c0;
                const float bb0 = b1s[col], bb1 = b1s[col + 1];
                float v0 = fmaxf(d1[nj][0] + bb0, 0.f);
                float v1 = fmaxf(d1[nj][1] + bb1, 0.f);
                float v2 = fmaxf(d1[nj][2] + bb0, 0.f);
                float v3 = fmaxf(d1[nj][3] + bb1, 0.f);
                *(uint32_t*)(smem + OFF_A2 + (uint32_t)((wm + r0) * AS2 + col) * 2)     = pack_rn(v0, v1);
                *(uint32_t*)(smem + OFF_A2 + (uint32_t)((wm + r0 + 8) * AS2 + col) * 2) = pack_rn(v2, v3);
            }
        }

        // ---- prefetch next tile (in flight during GEMM2) ----
        {
            int tn = t + NCTA;
            if (tn < NT) {
                int bn = tn >> 8, remn = tn & 255, hon = remn >> 1, wo0n = (remn & 1) * 64;
                const float* xb = x + ((size_t)bn * CC + q * 4) * (HH * WWID);
                int rw[3], cl[3];
                #pragma unroll
                for (int kk = 0; kk < 3; kk++) {
                    rw[kk] = refl(2 * hon + kk - 1, HH) * WWID;
                    cl[kk] = refl(2 * (wo0n + pos) + kk - 1, WWID);
                }
                #pragma unroll
                for (int ci = 0; ci < 4; ci++) {
                    const float* xc = xb + ci * (HH * WWID);
                    #pragma unroll
                    for (int kh = 0; kh < 3; kh++)
                        #pragma unroll
                        for (int kw = 0; kw < 3; kw++)
                            xv[ci * 9 + kh * 3 + kw] = __ldg(&xc[rw[kh] + cl[kw]]);
                }
            }
        }
        __syncthreads();   // A2 visible to all warps

        // ---- GEMM2: D2[64 x 144], warp covers 16m x 72n ----
        float d2[9][4];
        #pragma unroll
        for (int nj = 0; nj < 9; nj++)
            #pragma unroll
            for (int p = 0; p < 4; p++) d2[nj][p] = 0.f;
        {
            uint32_t pA = sb + OFF_A2 + (uint32_t)(arow * AS2 + khalf) * 2;
            uint32_t pB[4], pS;
            #pragma unroll
            for (int np = 0; np < 4; np++)
                pB[np] = sb + OFF_B2H + (uint32_t)((wn * 72 + np * 16 + (g & 1) * 8 + r) * AS2 + khalf) * 2;
            pS = sb + OFF_B2H + (uint32_t)((wn * 72 + 64 + r) * AS2 + g2 * 8) * 2;

            uint32_t a[4], bA[4][4], sA[2];
            #pragma unroll
            for (int ks = 0; ks < 8; ks++) {
                const uint32_t ko = ks * 32;
                ldsm4(a, pA + ko);
                #pragma unroll
                for (int np = 0; np < 4; np++) ldsm4(bA[np], pB[np] + ko);
                ldsm2(sA, pS + ko);
                #pragma unroll
                for (int np = 0; np < 4; np++) {
                    mma_f16(d2[np * 2],     a, bA[np][0], bA[np][2]);
                    mma_f16(d2[np * 2 + 1], a, bA[np][1], bA[np][3]);
                }
                mma_f16(d2[8], a, sA[0], sA[1]);
            }
        }

        // ---- epi2: D2 + b2 -> g_outp paired layout, half2 stores ----
        {
            const int r0 = lid >> 2;
            const int c0 = (lid & 3) * 2;
            // base for this (b): element offset of (col pair, pos) = col*LL + pos*2
            __half* ob = g_outp + (size_t)b * PP * LL + (size_t)(ho * 128 + wo0) * 2;
            const int posA = wm + r0;
            const int posB = posA + 8;
            #pragma unroll
            for (int nj = 0; nj < 9; nj++) {
                const int col = wn * 72 + nj * 8 + c0;   // even
                const float bb0 = b2s[col], bb1 = b2s[col + 1];
                __half* cp = ob + (size_t)col * LL;
                *(uint32_t*)(cp + posA * 2) = pack_rn(d2[nj][0] + bb0, d2[nj][1] + bb1);
                *(uint32_t*)(cp + posB * 2) = pack_rn(d2[nj][2] + bb0, d2[nj][3] + bb1);
            }
        }
    }
}

// ---------------------------------------------------------------------------
// Kernel B: branchless 4-contributor gather-fold + normalize + channel mix +
// softmax + modulate. Paired-column scratch layout.
// ---------------------------------------------------------------------------
__global__ __launch_bounds__(256)
void fold_softmax_kernel(const float* __restrict__ Wc, const float* __restrict__ bc,
                         float* __restrict__ out) {
    __shared__ float sWc[256];
    __shared__ float sbc[16];
    int tid = threadIdx.x;
    sWc[tid] = Wc[tid];
    if (tid < 16) sbc[tid] = bc[tid];
    __syncthreads();

    const int b = blockIdx.x >> 8;
    const int i = (blockIdx.x & 255) + 1;   // padded row in [1,256]
    const int j = tid + 1;                  // padded col in [1,256]

    // h-axis contributors (kh, ho, weight)
    int kh0, kh1, ho0, ho1; float wh0, wh1;
    if (i & 1) { kh0 = 1; ho0 = (i - 1) >> 1; wh0 = 1.f; kh1 = 1; ho1 = ho0; wh1 = 0.f; }
    else {
        kh0 = 0; ho0 = i >> 1; wh0 = (ho0 <= 127) ? 1.f : 0.f; if (ho0 > 127) ho0 = 127;
        kh1 = 2; ho1 = (i - 2) >> 1; wh1 = 1.f;
    }
    // w-axis contributors
    int kw0, kw1, wo0, wo1; float ww0, ww1;
    if (j & 1) { kw0 = 1; wo0 = (j - 1) >> 1; ww0 = 1.f; kw1 = 1; wo1 = wo0; ww1 = 0.f; }
    else {
        kw0 = 0; wo0 = j >> 1; ww0 = (wo0 <= 127) ? 1.f : 0.f; if (wo0 > 127) wo0 = 127;
        kw1 = 2; wo1 = (j - 2) >> 1; ww1 = 1.f;
    }

    const __half* gb = g_outp + (size_t)b * PP * LL;
    // paired layout: elem(p, l) at (p&~1)*LL + l*2 + (p&1)
    const int kk00 = kh0 * 3 + kw0, kk01 = kh0 * 3 + kw1;
    const int kk10 = kh1 * 3 + kw0, kk11 = kh1 * 3 + kw1;
    const int l00 = ho0 * 128 + wo0, l01 = ho0 * 128 + wo1;
    const int l10 = ho1 * 128 + wo0, l11 = ho1 * 128 + wo1;
    const float w00 = wh0 * ww0, w01 = wh0 * ww1, w10 = wh1 * ww0, w11 = wh1 * ww1;

    float nrm[16];
    #pragma unroll
    for (int c = 0; c < 16; c++) {
        const int p0 = c * 9;
        const int pA = p0 + kk00, pB = p0 + kk01, pC = p0 + kk10, pD = p0 + kk11;
        float vA = __half2float(__ldg(gb + (size_t)(pA & ~1) * LL + l00 * 2 + (pA & 1)));
        float vB = __half2float(__ldg(gb + (size_t)(pB & ~1) * LL + l01 * 2 + (pB & 1)));
        float vC = __half2float(__ldg(gb + (size_t)(pC & ~1) * LL + l10 * 2 + (pC & 1)));
        float vD = __half2float(__ldg(gb + (size_t)(pD & ~1) * LL + l11 * 2 + (pD & 1)));
        nrm[c] = w00 * vA + w01 * vB + w10 * vC + w11 * vD;
    }

    const float inv = 1.f / ((wh0 + wh1) * (ww0 + ww1) + 1e-6f);
    #pragma unroll
    for (int c = 0; c < 16; c++) nrm[c] *= inv;

    float logit[16];
    #pragma unroll
    for (int o = 0; o < 16; o++) {
        float s = sbc[o];
        #pragma unroll
        for (int c = 0; c < 16; c++) s += sWc[o * 16 + c] * nrm[c];
        logit[o] = s;
    }
    float m = logit[0];
    #pragma unroll
    for (int o = 1; o < 16; o++) m = fmaxf(m, logit[o]);
    float e[16], sum = 0.f;
    #pragma unroll
    for (int o = 0; o < 16; o++) { e[o] = __expf(logit[o] - m); sum += e[o]; }
    const float rs = 1.f / sum;

    float* ob = out + (size_t)b * CC * HH * WWID + (size_t)(i - 1) * WWID + (j - 1);
    #pragma unroll
    for (int c = 0; c < 16; c++) ob[(size_t)c * HH * WWID] = nrm[c] * e[c] * rs;
}

// ---------------------------------------------------------------------------
extern "C" void kernel_launch(void* const* d_in, const int* in_sizes, int n_in,
                              void* d_out, int out_size) {
    const float* x  = (const float*)d_in[0];
    const float* W1 = (const float*)d_in[1];
    const float* b1 = (const float*)d_in[2];
    const float* W2 = (const float*)d_in[3];
    const float* b2 = (const float*)d_in[4];
    const float* Wc = (const float*)d_in[5];
    const float* bc = (const float*)d_in[6];
    float* out = (float*)d_out;

    cudaFuncSetAttribute(mlp_persist, cudaFuncAttributeMaxDynamicSharedMemorySize, SMEM_TOT);

    mlp_persist<<<NCTA, 256, SMEM_TOT>>>(x, W1, b1, W2, b2);
    fold_softmax_kernel<<<BB * 256, 256>>>(Wc, bc, out);
}

// round 12
// speedup vs baseline: 1.8225x; 1.1140x over previous
#include <cuda_runtime.h>
#include <cuda_fp16.h>
#include <cstdint>

#define BB   32
#define CC   16
#define HH   256
#define WWID 256
#define PP   144
#define HID  128
#define LL   16384
#define NT   8192      // tiles: 64 positions each
#define NCTA 152

// Scratch for out_p, layout (B, 9, L, 16) fp16 = 151 MB
// element (b, kk, l, c): offset ((b*9 + kk)*LL + l)*16 + c
__device__ __half g_outp[(size_t)BB * PP * LL];

// ---------------- smem byte offsets ----------------
#define OFF_B1H 0                  // 128 x 152 x 2B = 38912 (fp16 W1^T)
#define OFF_B2H 38912              // 144 x 136 x 2B = 39168 (fp16 W2^T, n'-order)
#define OFF_A1  78080              // 64 x 152 x 2B = 19456 (A1, fp16)
#define OFF_A2  97536              // 64 x 136 x 2B = 17408 (A2, fp16)
#define OFF_b1  114944             // 512
#define OFF_b2  115456             // 576 (n'-order)
#define SMEM_TOT 116032
#define AS1 152                    // 304B rows: 19*16B -> conflict-free ldmatrix
#define AS2 136                    // 272B rows: 17*16B

// ---------------- helpers ----------------
__device__ __forceinline__ uint32_t smem_u32(const void* p) {
    uint32_t a;
    asm("{ .reg .u64 t; cvta.to.shared.u64 t, %1; cvt.u32.u64 %0, t; }" : "=r"(a) : "l"(p));
    return a;
}
__device__ __forceinline__ void ldsm4(uint32_t* r, uint32_t a) {
    asm volatile("ldmatrix.sync.aligned.m8n8.x4.shared.b16 {%0,%1,%2,%3}, [%4];"
                 : "=r"(r[0]), "=r"(r[1]), "=r"(r[2]), "=r"(r[3]) : "r"(a));
}
__device__ __forceinline__ void ldsm2(uint32_t* r, uint32_t a) {
    asm volatile("ldmatrix.sync.aligned.m8n8.x2.shared.b16 {%0,%1}, [%2];"
                 : "=r"(r[0]), "=r"(r[1]) : "r"(a));
}
__device__ __forceinline__ void mma_f16(float* d, const uint32_t* a, uint32_t b0, uint32_t b1) {
    asm volatile("mma.sync.aligned.m16n8k16.row.col.f32.f16.f16.f32 "
                 "{%0,%1,%2,%3}, {%4,%5,%6,%7}, {%8,%9}, {%0,%1,%2,%3};"
                 : "+f"(d[0]), "+f"(d[1]), "+f"(d[2]), "+f"(d[3])
                 : "r"(a[0]), "r"(a[1]), "r"(a[2]), "r"(a[3]), "r"(b0), "r"(b1));
}
// single-instruction packed f32x2 -> f16x2 convert
__device__ __forceinline__ uint32_t pack_rn(float v0, float v1) {
    __half2 h = __float22half2_rn(make_float2(v0, v1));
    return *(uint32_t*)&h;
}
__device__ __forceinline__ int refl(int v, int n) {
    return (v < 0) ? -v : ((v >= n) ? 2 * n - 2 - v : v);
}

// ---------------------------------------------------------------------------
// Persistent MLP kernel. grid = NCTA, 256 threads (8 warps: 4m x 2n).
// GEMM2 n-axis permuted to n' = kk*16 + c so epi2 writes (B,9,L,16) coalesced.
// ---------------------------------------------------------------------------
__global__ __launch_bounds__(256, 1)
void mlp_persist(const float* __restrict__ x, const float* __restrict__ W1,
                 const float* __restrict__ b1, const float* __restrict__ W2,
                 const float* __restrict__ b2) {
    extern __shared__ char smem[];
    const uint32_t sb = smem_u32(smem);
    const int tid = threadIdx.x;
    const int wid = tid >> 5, lid = tid & 31;

    float* b1s = (float*)(smem + OFF_b1);
    float* b2s = (float*)(smem + OFF_b2);
    if (tid < 128) b1s[tid] = b1[tid];
    if (tid < 144) b2s[tid] = b2[(tid & 15) * 9 + (tid >> 4)];   // b2s[n'] = b2[p(n')]

    // ---- stage fp16 W1^T ONCE ----
    #pragma unroll 4
    for (int i = 0; i < 72; i++) {
        int e = i * 256 + tid;               // e = k*128 + n
        int k = e >> 7, n = e & 127;
        __half h = __float2half_rn(__ldg(&W1[e]));
        *(uint16_t*)(smem + OFF_B1H + (uint32_t)(n * AS1 + k) * 2) = *(uint16_t*)&h;
    }
    // ---- stage fp16 W2^T ONCE, rows in n' = kk*16 + c order ----
    #pragma unroll 4
    for (int i = 0; i < 72; i++) {
        int e = i * 256 + tid;               // e = k*144 + p
        int k = e / 144, p = e - k * 144;
        int c = p / 9, kk = p - c * 9;
        int np = kk * 16 + c;
        __half h = __float2half_rn(__ldg(&W2[e]));
        *(uint16_t*)(smem + OFF_B2H + (uint32_t)(np * AS2 + k) * 2) = *(uint16_t*)&h;
    }

    // warp tiling constants
    const int wm = (wid & 3) * 16;
    const int wn = wid >> 2;
    const int g = lid >> 3, r = lid & 7;
    const int khalf = (g >> 1) * 8;
    const int arow = wm + (g & 1) * 8 + r;
    const int g2 = (lid >> 3) & 1;

    // gather mapping: pos = tid>>2 (64 pos), quarter q = tid&3 -> 36 p-elems
    const int pos = tid >> 2;
    const int q   = tid & 3;
    const int pb  = q * 36;

    float xv[36];

    // ---- prefetch first tile ----
    {
        int t = blockIdx.x;
        int b = t >> 8, rem = t & 255, ho = rem >> 1, wo0 = (rem & 1) * 64;
        const float* xb = x + ((size_t)b * CC + q * 4) * (HH * WWID);
        int rw[3], cl[3];
        #pragma unroll
        for (int kk = 0; kk < 3; kk++) {
            rw[kk] = refl(2 * ho + kk - 1, HH) * WWID;
            cl[kk] = refl(2 * (wo0 + pos) + kk - 1, WWID);
        }
        #pragma unroll
        for (int ci = 0; ci < 4; ci++) {
            const float* xc = xb + ci * (HH * WWID);
            #pragma unroll
            for (int kh = 0; kh < 3; kh++)
                #pragma unroll
                for (int kw = 0; kw < 3; kw++)
                    xv[ci * 9 + kh * 3 + kw] = __ldg(&xc[rw[kh] + cl[kw]]);
        }
    }

    for (int t = blockIdx.x; t < NT; t += NCTA) {
        const int b = t >> 8, rem = t & 255, ho = rem >> 1, wo0 = (rem & 1) * 64;

        // ---- store A1 (fp16) ----
        #pragma unroll
        for (int i = 0; i < 18; i++) {
            uint32_t hi = pack_rn(xv[2 * i], xv[2 * i + 1]);
            uint32_t off = (uint32_t)(pos * AS1 + pb + 2 * i) * 2;
            *(uint32_t*)(smem + OFF_A1 + off) = hi;
        }
        __syncthreads();   // A1 complete; orders prev GEMM2 before epi1

        // ---- GEMM1: D1[64 x 128], warp covers 16m x 64n ----
        float d1[8][4];
        #pragma unroll
        for (int nj = 0; nj < 8; nj++)
            #pragma unroll
            for (int p = 0; p < 4; p++) d1[nj][p] = 0.f;
        {
            uint32_t pA = sb + OFF_A1 + (uint32_t)(arow * AS1 + khalf) * 2;
            uint32_t pB[4];
            #pragma unroll
            for (int np = 0; np < 4; np++)
                pB[np] = sb + OFF_B1H + (uint32_t)((wn * 64 + np * 16 + (g & 1) * 8 + r) * AS1 + khalf) * 2;

            uint32_t a[4], bA[4][4];
            #pragma unroll
            for (int ks = 0; ks < 9; ks++) {
                const uint32_t ko = ks * 32;
                ldsm4(a, pA + ko);
                #pragma unroll
                for (int np = 0; np < 4; np++) ldsm4(bA[np], pB[np] + ko);
                #pragma unroll
                for (int np = 0; np < 4; np++) {
                    mma_f16(d1[np * 2],     a, bA[np][0], bA[np][2]);
                    mma_f16(d1[np * 2 + 1], a, bA[np][1], bA[np][3]);
                }
            }
        }

        // ---- epi1: relu(D1+b1) fp16 -> A2 (separate buffer, no sync) ----
        {
            const int r0 = lid >> 2;
            const int c0 = (lid & 3) * 2;
            #pragma unroll
            for (int nj = 0; nj < 8; nj++) {
                const int col = wn * 64 + nj * 8 + c0;
                const float bb0 = b1s[col], bb1 = b1s[col + 1];
                float v0 = fmaxf(d1[nj][0] + bb0, 0.f);
                float v1 = fmaxf(d1[nj][1] + bb1, 0.f);
                float v2 = fmaxf(d1[nj][2] + bb0, 0.f);
                float v3 = fmaxf(d1[nj][3] + bb1, 0.f);
                *(uint32_t*)(smem + OFF_A2 + (uint32_t)((wm + r0) * AS2 + col) * 2)     = pack_rn(v0, v1);
                *(uint32_t*)(smem + OFF_A2 + (uint32_t)((wm + r0 + 8) * AS2 + col) * 2) = pack_rn(v2, v3);
            }
        }

        // ---- prefetch next tile (in flight during GEMM2) ----
        {
            int tn = t + NCTA;
            if (tn < NT) {
                int bn = tn >> 8, remn = tn & 255, hon = remn >> 1, wo0n = (remn & 1) * 64;
                const float* xb = x + ((size_t)bn * CC + q * 4) * (HH * WWID);
                int rw[3], cl[3];
                #pragma unroll
                for (int kk = 0; kk < 3; kk++) {
                    rw[kk] = refl(2 * hon + kk - 1, HH) * WWID;
                    cl[kk] = refl(2 * (wo0n + pos) + kk - 1, WWID);
                }
                #pragma unroll
                for (int ci = 0; ci < 4; ci++) {
                    const float* xc = xb + ci * (HH * WWID);
                    #pragma unroll
                    for (int kh = 0; kh < 3; kh++)
                        #pragma unroll
                        for (int kw = 0; kw < 3; kw++)
                            xv[ci * 9 + kh * 3 + kw] = __ldg(&xc[rw[kh] + cl[kw]]);
                }
            }
        }
        __syncthreads();   // A2 visible to all warps

        // ---- GEMM2: D2[64 x 144 (n'-order)], warp covers 16m x 72n ----
        float d2[9][4];
        #pragma unroll
        for (int nj = 0; nj < 9; nj++)
            #pragma unroll
            for (int p = 0; p < 4; p++) d2[nj][p] = 0.f;
        {
            uint32_t pA = sb + OFF_A2 + (uint32_t)(arow * AS2 + khalf) * 2;
            uint32_t pB[4], pS;
            #pragma unroll
            for (int np = 0; np < 4; np++)
                pB[np] = sb + OFF_B2H + (uint32_t)((wn * 72 + np * 16 + (g & 1) * 8 + r) * AS2 + khalf) * 2;
            pS = sb + OFF_B2H + (uint32_t)((wn * 72 + 64 + r) * AS2 + g2 * 8) * 2;

            uint32_t a[4], bA[4][4], sA[2];
            #pragma unroll
            for (int ks = 0; ks < 8; ks++) {
                const uint32_t ko = ks * 32;
                ldsm4(a, pA + ko);
                #pragma unroll
                for (int np = 0; np < 4; np++) ldsm4(bA[np], pB[np] + ko);
                ldsm2(sA, pS + ko);
                #pragma unroll
                for (int np = 0; np < 4; np++) {
                    mma_f16(d2[np * 2],     a, bA[np][0], bA[np][2]);
                    mma_f16(d2[np * 2 + 1], a, bA[np][1], bA[np][3]);
                }
                mma_f16(d2[8], a, sA[0], sA[1]);
            }
        }

        // ---- epi2: D2 + b2 -> g_outp (B,9,L,16), coalesced half2 stores ----
        {
            const int r0 = lid >> 2;
            const int c0 = (lid & 3) * 2;
            const int posA = wm + r0;
            const int posB = posA + 8;
            const size_t lbase = (size_t)(ho * 128 + wo0);
            #pragma unroll
            for (int nj = 0; nj < 9; nj++) {
                const int np = wn * 72 + nj * 8 + c0;   // n'
                const int kk = np >> 4, c = np & 15;
                const float bb0 = b2s[np], bb1 = b2s[np + 1];
                __half* cp = g_outp + ((size_t)(b * 9 + kk) * LL + lbase) * 16 + c;
                *(uint32_t*)(cp + posA * 16) = pack_rn(d2[nj][0] + bb0, d2[nj][1] + bb1);
                *(uint32_t*)(cp + posB * 16) = pack_rn(d2[nj][2] + bb0, d2[nj][3] + bb1);
            }
        }
    }
}

// ---------------------------------------------------------------------------
// Kernel B: vectorized gather-fold (8x LDG.128/thread) + normalize +
// channel mix + softmax + modulate.
// ---------------------------------------------------------------------------
__global__ __launch_bounds__(256)
void fold_softmax_kernel(const float* __restrict__ Wc, const float* __restrict__ bc,
                         float* __restrict__ out) {
    __shared__ float sWc[256];
    __shared__ float sbc[16];
    int tid = threadIdx.x;
    sWc[tid] = Wc[tid];
    if (tid < 16) sbc[tid] = bc[tid];
    __syncthreads();

    const int b = blockIdx.x >> 8;
    const int i = (blockIdx.x & 255) + 1;   // padded row in [1,256]
    const int j = tid + 1;                  // padded col in [1,256]

    // h-axis contributors (kh, ho, weight)
    int kh0, kh1, ho0, ho1; float wh0, wh1;
    if (i & 1) { kh0 = 1; ho0 = (i - 1) >> 1; wh0 = 1.f; kh1 = 1; ho1 = ho0; wh1 = 0.f; }
    else {
        kh0 = 0; ho0 = i >> 1; wh0 = (ho0 <= 127) ? 1.f : 0.f; if (ho0 > 127) ho0 = 127;
        kh1 = 2; ho1 = (i - 2) >> 1; wh1 = 1.f;
    }
    // w-axis contributors
    int kw0, kw1, wo0, wo1; float ww0, ww1;
    if (j & 1) { kw0 = 1; wo0 = (j - 1) >> 1; ww0 = 1.f; kw1 = 1; wo1 = wo0; ww1 = 0.f; }
    else {
        kw0 = 0; wo0 = j >> 1; ww0 = (wo0 <= 127) ? 1.f : 0.f; if (wo0 > 127) wo0 = 127;
        kw1 = 2; wo1 = (j - 2) >> 1; ww1 = 1.f;
    }

    float nrm[16];
    #pragma unroll
    for (int c = 0; c < 16; c++) nrm[c] = 0.f;

    const __half* gb = g_outp + (size_t)b * 9 * LL * 16;
    // accumulate one contributor record (16 channels = 2 x LDG.128)
    #define ACC_REC(KK, LV, W) do {                                            \
        const uint4* rp = (const uint4*)(gb + ((size_t)(KK) * LL + (LV)) * 16);\
        uint4 u0 = __ldg(rp), u1 = __ldg(rp + 1);                              \
        const __half2* h0 = (const __half2*)&u0;                               \
        const __half2* h1 = (const __half2*)&u1;                               \
        _Pragma("unroll")                                                      \
        for (int qq = 0; qq < 4; qq++) {                                       \
            float2 f0 = __half22float2(h0[qq]);                                \
            float2 f1 = __half22float2(h1[qq]);                                \
            nrm[2 * qq]     += (W) * f0.x;                                     \
            nrm[2 * qq + 1] += (W) * f0.y;                                     \
            nrm[8 + 2 * qq]     += (W) * f1.x;                                 \
            nrm[8 + 2 * qq + 1] += (W) * f1.y;                                 \
        }                                                                      \
    } while (0)

    const float w00 = wh0 * ww0, w01 = wh0 * ww1, w10 = wh1 * ww0, w11 = wh1 * ww1;
    ACC_REC(kh0 * 3 + kw0, ho0 * 128 + wo0, w00);
    ACC_REC(kh0 * 3 + kw1, ho0 * 128 + wo1, w01);
    ACC_REC(kh1 * 3 + kw0, ho1 * 128 + wo0, w10);
    ACC_REC(kh1 * 3 + kw1, ho1 * 128 + wo1, w11);
    #undef ACC_REC

    const float inv = 1.f / ((wh0 + wh1) * (ww0 + ww1) + 1e-6f);
    #pragma unroll
    for (int c = 0; c < 16; c++) nrm[c] *= inv;

    float logit[16];
    #pragma unroll
    for (int o = 0; o < 16; o++) {
        float s = sbc[o];
        #pragma unroll
        for (int c = 0; c < 16; c++) s += sWc[o * 16 + c] * nrm[c];
        logit[o] = s;
    }
    float m = logit[0];
    #pragma unroll
    for (int o = 1; o < 16; o++) m = fmaxf(m, logit[o]);
    float e[16], sum = 0.f;
    #pragma unroll
    for (int o = 0; o < 16; o++) { e[o] = __expf(logit[o] - m); sum += e[o]; }
    const float rs = 1.f / sum;

    float* ob = out + (size_t)b * CC * HH * WWID + (size_t)(i - 1) * WWID + (j - 1);
    #pragma unroll
    for (int c = 0; c < 16; c++) ob[(size_t)c * HH * WWID] = nrm[c] * e[c] * rs;
}

// ---------------------------------------------------------------------------
extern "C" void kernel_launch(void* const* d_in, const int* in_sizes, int n_in,
                              void* d_out, int out_size) {
    const float* x  = (const float*)d_in[0];
    const float* W1 = (const float*)d_in[1];
    const float* b1 = (const float*)d_in[2];
    const float* W2 = (const float*)d_in[3];
    const float* b2 = (const float*)d_in[4];
    const float* Wc = (const float*)d_in[5];
    const float* bc = (const float*)d_in[6];
    float* out = (float*)d_out;

    cudaFuncSetAttribute(mlp_persist, cudaFuncAttributeMaxDynamicSharedMemorySize, SMEM_TOT);

    mlp_persist<<<NCTA, 256, SMEM_TOT>>>(x, W1, b1, W2, b2);
    fold_softmax_kernel<<<BB * 256, 256>>>(Wc, bc, out);
}